// round 5
// baseline (speedup 1.0000x reference)
#include <cuda_runtime.h>

#define NMAX   100000
#define EMAX   1600000
#define DIN    64
#define DHID   64
#define DOUT   32

// ---------------- scratch (no allocations allowed) ----------------
// INVARIANT: g_deg is all-zero at the start of every kernel_launch run.
// (BSS-zero initially; re-zeroed by k_agg32 at the end of every run.)
__device__ int   g_deg[NMAX];
__device__ int   g_off[NMAX];
__device__ int   g_cur[NMAX];
__device__ int   g_csr[EMAX];
__device__ __align__(16) float g_p1[NMAX * DHID];   // x @ W1l
__device__ __align__(16) float g_q1[NMAX * DHID];   // x @ W1r + b1
__device__ __align__(16) float g_h [NMAX * DHID];   // relu(agg(p1) + q1)
__device__ __align__(16) float g_p2[NMAX * DOUT];   // h @ W2l
__device__ __align__(16) float g_q2[NMAX * DOUT];   // h @ W2r + b2

// per-block int64-vs-int32 detection: int64 little-endian values < 1e5 have
// all odd 32-bit words == 0; for int32 those words are random src ids.
__device__ __forceinline__ int detect_m(const int* __restrict__ ei, int* s_m) {
    if (threadIdx.x == 0) {
        int orv = 0;
        #pragma unroll
        for (int k = 0; k < 64; k++) orv |= ei[2 * k + 1];
        *s_m = (orv == 0) ? 2 : 1;       // element stride in int32 words
    }
    __syncthreads();
    return *s_m;
}

// ---------------- count (relies on deg==0 invariant) ----------------
__global__ void k_count(const int* __restrict__ ei, int* deg, int E) {
    __shared__ int s_m;
    int m = detect_m(ei, &s_m);
    int e = blockIdx.x * blockDim.x + threadIdx.x;
    if (e < E) {
        int d = ei[((long long)E + e) * m];
        atomicAdd(&deg[d], 1);
    }
}

// ---------------- single-kernel exclusive scan (1 block, chunked) ----------------
__global__ __launch_bounds__(1024) void k_scan_one(
    const int* __restrict__ deg, int* off, int* cur, int n)
{
    __shared__ int wsum[32];
    int tid = threadIdx.x, lane = tid & 31, wid = tid >> 5;
    int carry = 0;
    int nchunks = (n + 4095) / 4096;
    for (int c = 0; c < nchunks; c++) {
        int base = c * 4096 + tid * 4;
        int4 v4 = make_int4(0, 0, 0, 0);
        if (base + 3 < n) v4 = *reinterpret_cast<const int4*>(deg + base);
        else {
            if (base     < n) v4.x = deg[base];
            if (base + 1 < n) v4.y = deg[base + 1];
            if (base + 2 < n) v4.z = deg[base + 2];
        }
        int s0 = v4.x, s1 = s0 + v4.y, s2 = s1 + v4.z, s3 = s2 + v4.w;
        int v = s3;
        #pragma unroll
        for (int d = 1; d < 32; d <<= 1) {
            int t = __shfl_up_sync(0xffffffffu, v, d);
            if (lane >= d) v += t;
        }
        if (lane == 31) wsum[wid] = v;
        __syncthreads();
        if (wid == 0) {
            int w = wsum[lane];
            #pragma unroll
            for (int d = 1; d < 32; d <<= 1) {
                int t = __shfl_up_sync(0xffffffffu, w, d);
                if (lane >= d) w += t;
            }
            wsum[lane] = w;
        }
        __syncthreads();
        int pre = carry + (wid > 0 ? wsum[wid - 1] : 0) + (v - s3);
        if (base     < n) { off[base]     = pre;      cur[base]     = pre;      }
        if (base + 1 < n) { off[base + 1] = pre + s0; cur[base + 1] = pre + s0; }
        if (base + 2 < n) { off[base + 2] = pre + s1; cur[base + 2] = pre + s1; }
        if (base + 3 < n) { off[base + 3] = pre + s2; cur[base + 3] = pre + s2; }
        int total = wsum[31];
        __syncthreads();
        carry += total;
    }
}

// ---------------- fused: CSR scatter + dual GEMM64 (independent work) ----------------
// blocks [0, SB): scatter; blocks [SB, SB+GB): gemm (MT=32 nodes, DO=64).
#define GEMM64_MT 32
__global__ __launch_bounds__(256) void k_scatter_gemm64(
    const int* __restrict__ ei, int* cur, int* csr, int E, int SB,
    const float* __restrict__ x, const float* __restrict__ Wl,
    const float* __restrict__ Wr, const float* __restrict__ b,
    float* __restrict__ p, float* __restrict__ q, int n)
{
    constexpr int MT = GEMM64_MT, DO = 64, NC = 128, TN = 32;
    __shared__ float sXT[64][MT + 4];
    __shared__ float sW [64][NC];

    if ((int)blockIdx.x < SB) {
        __shared__ int s_m;
        int m = detect_m(ei, &s_m);
        int e = blockIdx.x * 256 + threadIdx.x;
        if (e < E) {
            int s = ei[(long long)e * m];
            int d = ei[((long long)E + e) * m];
            int pos = atomicAdd(&cur[d], 1);
            csr[pos] = s;
        }
        return;
    }

    int t = threadIdx.x;
    int nodeBase = ((int)blockIdx.x - SB) * MT;

    for (int i = t; i < 64 * NC; i += 256) {
        int k = i / NC, c = i % NC;
        sW[k][c] = (c < DO) ? Wl[k * DO + c] : Wr[k * DO + (c - DO)];
    }
    constexpr int F4 = MT * 16 / 256;
    #pragma unroll
    for (int i = 0; i < F4; i++) {
        int flat = t + i * 256;
        int nd = flat >> 4, k4 = (flat & 15) * 4;
        int node = nodeBase + nd;
        float4 v = make_float4(0.f, 0.f, 0.f, 0.f);
        if (node < n) v = *reinterpret_cast<const float4*>(x + (size_t)node * 64 + k4);
        sXT[k4 + 0][nd] = v.x;
        sXT[k4 + 1][nd] = v.y;
        sXT[k4 + 2][nd] = v.z;
        sXT[k4 + 3][nd] = v.w;
    }
    __syncthreads();

    int tn = t % TN, tm = t / TN;
    float acc[4][4];
    #pragma unroll
    for (int r = 0; r < 4; r++)
        #pragma unroll
        for (int c = 0; c < 4; c++) acc[r][c] = 0.0f;

    #pragma unroll 8
    for (int k = 0; k < 64; k++) {
        float4 bv = *reinterpret_cast<const float4*>(&sW[k][tn * 4]);
        float4 av = *reinterpret_cast<const float4*>(&sXT[k][tm * 4]);
        float a[4] = {av.x, av.y, av.z, av.w};
        float bb[4] = {bv.x, bv.y, bv.z, bv.w};
        #pragma unroll
        for (int r = 0; r < 4; r++)
            #pragma unroll
            for (int c = 0; c < 4; c++)
                acc[r][c] = fmaf(a[r], bb[c], acc[r][c]);
    }

    int cbase = tn * 4;
    bool isQ = (cbase >= DO);
    int col = isQ ? (cbase - DO) : cbase;
    float4 bias = make_float4(0.f, 0.f, 0.f, 0.f);
    if (isQ) bias = *reinterpret_cast<const float4*>(b + col);
    float* dst = isQ ? q : p;
    #pragma unroll
    for (int r = 0; r < 4; r++) {
        int node = nodeBase + tm * 4 + r;
        if (node < n) {
            float4 o;
            o.x = acc[r][0] + bias.x; o.y = acc[r][1] + bias.y;
            o.z = acc[r][2] + bias.z; o.w = acc[r][3] + bias.w;
            *reinterpret_cast<float4*>(dst + (size_t)node * DO + col) = o;
        }
    }
}

// ---------------- dual GEMM (layer 2, standalone): MT=64, DO=32 ----------------
__global__ __launch_bounds__(256) void k_gemm32(
    const float* __restrict__ x, const float* __restrict__ Wl,
    const float* __restrict__ Wr, const float* __restrict__ b,
    float* __restrict__ p, float* __restrict__ q, int n)
{
    constexpr int MT = 64, DO = 32, NC = 64, TN = 16;
    __shared__ float sXT[64][MT + 4];
    __shared__ float sW [64][NC];
    int t = threadIdx.x;
    int nodeBase = blockIdx.x * MT;

    for (int i = t; i < 64 * NC; i += 256) {
        int k = i / NC, c = i % NC;
        sW[k][c] = (c < DO) ? Wl[k * DO + c] : Wr[k * DO + (c - DO)];
    }
    constexpr int F4 = MT * 16 / 256;
    #pragma unroll
    for (int i = 0; i < F4; i++) {
        int flat = t + i * 256;
        int nd = flat >> 4, k4 = (flat & 15) * 4;
        int node = nodeBase + nd;
        float4 v = make_float4(0.f, 0.f, 0.f, 0.f);
        if (node < n) v = *reinterpret_cast<const float4*>(x + (size_t)node * 64 + k4);
        sXT[k4 + 0][nd] = v.x;
        sXT[k4 + 1][nd] = v.y;
        sXT[k4 + 2][nd] = v.z;
        sXT[k4 + 3][nd] = v.w;
    }
    __syncthreads();

    int tn = t % TN, tm = t / TN;
    float acc[4][4];
    #pragma unroll
    for (int r = 0; r < 4; r++)
        #pragma unroll
        for (int c = 0; c < 4; c++) acc[r][c] = 0.0f;

    #pragma unroll 8
    for (int k = 0; k < 64; k++) {
        float4 bv = *reinterpret_cast<const float4*>(&sW[k][tn * 4]);
        float4 av = *reinterpret_cast<const float4*>(&sXT[k][tm * 4]);
        float a[4] = {av.x, av.y, av.z, av.w};
        float bb[4] = {bv.x, bv.y, bv.z, bv.w};
        #pragma unroll
        for (int r = 0; r < 4; r++)
            #pragma unroll
            for (int c = 0; c < 4; c++)
                acc[r][c] = fmaf(a[r], bb[c], acc[r][c]);
    }

    int cbase = tn * 4;
    bool isQ = (cbase >= DO);
    int col = isQ ? (cbase - DO) : cbase;
    float4 bias = make_float4(0.f, 0.f, 0.f, 0.f);
    if (isQ) bias = *reinterpret_cast<const float4*>(b + col);
    float* dst = isQ ? q : p;
    #pragma unroll
    for (int r = 0; r < 4; r++) {
        int node = nodeBase + tm * 4 + r;
        if (node < n) {
            float4 o;
            o.x = acc[r][0] + bias.x; o.y = acc[r][1] + bias.y;
            o.z = acc[r][2] + bias.z; o.w = acc[r][3] + bias.w;
            *reinterpret_cast<float4*>(dst + (size_t)node * DO + col) = o;
        }
    }
}

// ---------------- aggregation: one warp per node, 16-wide MLP ----------------
__global__ __launch_bounds__(256) void k_agg64_relu(
    const float* __restrict__ p, const float* __restrict__ q,
    const int* __restrict__ off, const int* __restrict__ deg,
    const int* __restrict__ csr, float* __restrict__ h, int n)
{
    int warp = (blockIdx.x * blockDim.x + threadIdx.x) >> 5;
    int lane = threadIdx.x & 31;
    if (warp >= n) return;
    int o = off[warp];
    int d = deg[warp];
    float ax = 0.0f, ay = 0.0f;
    int e = 0;
    for (; e + 16 <= d; e += 16) {
        float2 v[16];
        #pragma unroll
        for (int i = 0; i < 16; i++) {
            int s = __ldg(&csr[o + e + i]);
            v[i] = __ldg((const float2*)(p + (size_t)s * 64 + lane * 2));
        }
        float x0 = 0.f, y0 = 0.f, x1 = 0.f, y1 = 0.f;
        #pragma unroll
        for (int i = 0; i < 16; i += 2) {
            x0 += v[i].x;     y0 += v[i].y;
            x1 += v[i + 1].x; y1 += v[i + 1].y;
        }
        ax += x0 + x1; ay += y0 + y1;
    }
    for (; e + 4 <= d; e += 4) {
        float2 v[4];
        #pragma unroll
        for (int i = 0; i < 4; i++) {
            int s = __ldg(&csr[o + e + i]);
            v[i] = __ldg((const float2*)(p + (size_t)s * 64 + lane * 2));
        }
        ax += (v[0].x + v[1].x) + (v[2].x + v[3].x);
        ay += (v[0].y + v[1].y) + (v[2].y + v[3].y);
    }
    for (; e < d; e++) {
        int s = __ldg(&csr[o + e]);
        float2 v = __ldg((const float2*)(p + (size_t)s * 64 + lane * 2));
        ax += v.x; ay += v.y;
    }
    float inv = 1.0f / (float)max(d, 1);
    float2 qq = __ldg((const float2*)(q + (size_t)warp * 64 + lane * 2));
    float2 out;
    out.x = fmaxf(fmaf(ax, inv, qq.x), 0.0f);
    out.y = fmaxf(fmaf(ay, inv, qq.y), 0.0f);
    *reinterpret_cast<float2*>(h + (size_t)warp * 64 + lane * 2) = out;
}

// final aggregation + restore deg==0 invariant for the next run
__global__ __launch_bounds__(256) void k_agg32(
    const float* __restrict__ p, const float* __restrict__ q,
    const int* __restrict__ off, int* deg,
    const int* __restrict__ csr, float* __restrict__ out, int n)
{
    int warp = (blockIdx.x * blockDim.x + threadIdx.x) >> 5;
    int lane = threadIdx.x & 31;
    if (warp >= n) return;
    int o = off[warp];
    int d = deg[warp];
    if (lane == 0) deg[warp] = 0;     // restore invariant (this warp owns deg[warp])
    float a = 0.0f;
    int e = 0;
    for (; e + 16 <= d; e += 16) {
        float v[16];
        #pragma unroll
        for (int i = 0; i < 16; i++) {
            int s = __ldg(&csr[o + e + i]);
            v[i] = __ldg(p + (size_t)s * 32 + lane);
        }
        float a0 = 0.f, a1 = 0.f;
        #pragma unroll
        for (int i = 0; i < 16; i += 2) { a0 += v[i]; a1 += v[i + 1]; }
        a += a0 + a1;
    }
    for (; e + 4 <= d; e += 4) {
        float v[4];
        #pragma unroll
        for (int i = 0; i < 4; i++) {
            int s = __ldg(&csr[o + e + i]);
            v[i] = __ldg(p + (size_t)s * 32 + lane);
        }
        a += (v[0] + v[1]) + (v[2] + v[3]);
    }
    for (; e < d; e++) {
        int s = __ldg(&csr[o + e]);
        a += __ldg(p + (size_t)s * 32 + lane);
    }
    float inv = 1.0f / (float)max(d, 1);
    out[(size_t)warp * 32 + lane] = fmaf(a, inv, q[(size_t)warp * 32 + lane]);
}

// ---------------- launcher ----------------
extern "C" void kernel_launch(void* const* d_in, const int* in_sizes, int n_in,
                              void* d_out, int out_size)
{
    const float* x   = (const float*)d_in[0];
    const int*   ei  = (const int*)d_in[1];     // int32 view; per-block dtype detect
    const float* W1l = (const float*)d_in[2];
    const float* b1l = (const float*)d_in[3];
    const float* W1r = (const float*)d_in[4];
    const float* W2l = (const float*)d_in[5];
    const float* b2l = (const float*)d_in[6];
    const float* W2r = (const float*)d_in[7];
    float* out = (float*)d_out;

    int n = in_sizes[0] / DIN;     // 100000
    int E = in_sizes[1] / 2;       // 1600000

    int SB = (E + 255) / 256;                    // scatter blocks
    int GB = (n + GEMM64_MT - 1) / GEMM64_MT;    // gemm64 blocks

    // idx 0..2: CSR + layer-1 transform
    k_count<<<SB, 256>>>(ei, g_deg, E);
    k_scan_one<<<1, 1024>>>(g_deg, g_off, g_cur, n);
    k_scatter_gemm64<<<SB + GB, 256>>>(ei, g_cur, g_csr, E, SB,
                                       x, W1l, W1r, b1l, g_p1, g_q1, n);
    // idx 3: agg64 — ncu's fixed sample lands here this round
    k_agg64_relu<<<(n + 7) / 8, 256>>>(g_p1, g_q1, g_off, g_deg, g_csr, g_h, n);
    // layer 2
    k_gemm32<<<(n + 63) / 64, 256>>>(g_h, W2l, W2r, b2l, g_p2, g_q2, n);
    k_agg32<<<(n + 7) / 8, 256>>>(g_p2, g_q2, g_off, g_deg, g_csr, out, n);
}

// round 6
// speedup vs baseline: 11.3145x; 11.3145x over previous
#include <cuda_runtime.h>

#define NMAX   100000
#define EMAX   1600000
#define NB     296            // 2 blocks/SM on 148+ SMs -> guaranteed co-resident
#define NT     256
#define GSZ    (NB * NT)
#define NWARPS (NB * 8)

// ---------------- persistent state (no allocations allowed) ----------------
// INVARIANT: g_deg all-zero at entry (BSS-zero first run; re-zeroed in last phase).
__device__ int g_bar_count;   // barrier arrival counter (returns to 0 after each barrier)
__device__ int g_bar_sense;   // barrier sense (persists; re-read at kernel start)
__device__ int g_deg[NMAX];
__device__ int g_off[NMAX];
__device__ int g_cur[NMAX];
__device__ int g_csr[EMAX];
__device__ __align__(16) float g_p1[NMAX * 64];
__device__ __align__(16) float g_q1[NMAX * 64];
__device__ __align__(16) float g_h [NMAX * 64];
__device__ __align__(16) float g_p2[NMAX * 32];
__device__ __align__(16) float g_q2[NMAX * 32];

// ---------------- grid-wide barrier (sense reversal, co-resident grid) ----------------
__device__ __forceinline__ void gbar(int& sns) {
    __syncthreads();
    if (threadIdx.x == 0) {
        sns ^= 1;
        __threadfence();
        if (atomicAdd(&g_bar_count, 1) == NB - 1) {
            atomicExch(&g_bar_count, 0);
            __threadfence();
            atomicExch(&g_bar_sense, sns);
        } else {
            while (atomicAdd(&g_bar_sense, 0) != sns) __nanosleep(64);
        }
        __threadfence();
    }
    __syncthreads();
}

// ---------------- the whole model in one launch ----------------
__global__ __launch_bounds__(NT, 2) void k_mono(
    const int* __restrict__ ei, const float* __restrict__ x,
    const float* __restrict__ W1l, const float* __restrict__ b1l,
    const float* __restrict__ W1r, const float* __restrict__ W2l,
    const float* __restrict__ b2l, const float* __restrict__ W2r,
    float* __restrict__ out, int n, int E)
{
    __shared__ __align__(16) float s_pool[10496];   // 41,984 B: gemm smem (reused)
    __shared__ int s_wsum[8];
    __shared__ int s_m;

    const int tid  = threadIdx.x;
    const int bid  = blockIdx.x;
    const int gtid = bid * NT + tid;
    const int lane = tid & 31;
    const int wid  = tid >> 5;

    // dtype detect: int64 LE values <1e5 -> all odd 32-bit words are 0
    if (tid == 0) {
        int orv = 0;
        #pragma unroll
        for (int k = 0; k < 64; k++) orv |= ei[2 * k + 1];
        s_m = (orv == 0) ? 2 : 1;
    }
    __syncthreads();
    const int m = s_m;

    int sns = 0;
    if (tid == 0) sns = g_bar_sense;

    // ===== Phase A: degree count (relies on deg==0 invariant) =====
    for (int e = gtid; e < E; e += GSZ) {
        int d = ei[((long long)E + e) * m];
        atomicAdd(&g_deg[d], 1);
    }
    gbar(sns);

    // ===== Phase B: block0 scans; blocks 1..NB-1 do layer-1 dual GEMM =====
    if (bid == 0) {
        int carry = 0;
        int nch = (n + 1023) >> 10;
        for (int c = 0; c < nch; c++) {
            int base = (c << 10) + tid * 4;
            int4 v4 = make_int4(0, 0, 0, 0);
            if (base + 3 < n) v4 = *reinterpret_cast<const int4*>(g_deg + base);
            else {
                if (base     < n) v4.x = g_deg[base];
                if (base + 1 < n) v4.y = g_deg[base + 1];
                if (base + 2 < n) v4.z = g_deg[base + 2];
            }
            int s0 = v4.x, s1 = s0 + v4.y, s2 = s1 + v4.z, s3 = s2 + v4.w;
            int v = s3;
            #pragma unroll
            for (int d = 1; d < 32; d <<= 1) {
                int t = __shfl_up_sync(0xffffffffu, v, d);
                if (lane >= d) v += t;
            }
            if (lane == 31) s_wsum[wid] = v;
            __syncthreads();
            if (tid < 8) {
                int w = s_wsum[tid];
                #pragma unroll
                for (int d = 1; d < 8; d <<= 1) {
                    int t = __shfl_up_sync(0xffu, w, d, 8);
                    if (tid >= d) w += t;
                }
                s_wsum[tid] = w;
            }
            __syncthreads();
            int pre = carry + (wid ? s_wsum[wid - 1] : 0) + (v - s3);
            if (base     < n) { g_off[base]     = pre;      g_cur[base]     = pre;      }
            if (base + 1 < n) { g_off[base + 1] = pre + s0; g_cur[base + 1] = pre + s0; }
            if (base + 2 < n) { g_off[base + 2] = pre + s1; g_cur[base + 2] = pre + s1; }
            if (base + 3 < n) { g_off[base + 3] = pre + s2; g_cur[base + 3] = pre + s2; }
            int tot = s_wsum[7];
            __syncthreads();
            carry += tot;
        }
    } else {
        // gemm64: p1 = x@W1l, q1 = x@W1r + b1; MT=32 nodes/tile, NC=128 cols
        float* sW = s_pool;                                   // [64][128]
        float (*sXT)[36] = (float(*)[36])(s_pool + 8192);     // [64][36]
        for (int i = tid; i < 64 * 128; i += NT) {
            int k = i >> 7, c = i & 127;
            sW[i] = (c < 64) ? W1l[k * 64 + c] : W1r[k * 64 + (c - 64)];
        }
        int ntiles = (n + 31) >> 5;
        for (int t = bid - 1; t < ntiles; t += NB - 1) {
            int nodeBase = t << 5;
            __syncthreads();
            #pragma unroll
            for (int i = 0; i < 2; i++) {
                int flat = tid + i * NT;
                int nd = flat >> 4, k4 = (flat & 15) * 4;
                int node = nodeBase + nd;
                float4 v = make_float4(0.f, 0.f, 0.f, 0.f);
                if (node < n) v = *reinterpret_cast<const float4*>(x + (size_t)node * 64 + k4);
                sXT[k4 + 0][nd] = v.x; sXT[k4 + 1][nd] = v.y;
                sXT[k4 + 2][nd] = v.z; sXT[k4 + 3][nd] = v.w;
            }
            __syncthreads();
            int tn = tid & 31, tm = tid >> 5;
            float acc[4][4];
            #pragma unroll
            for (int r = 0; r < 4; r++)
                #pragma unroll
                for (int c = 0; c < 4; c++) acc[r][c] = 0.0f;
            #pragma unroll 8
            for (int k = 0; k < 64; k++) {
                float4 bv = *reinterpret_cast<const float4*>(&sW[k * 128 + tn * 4]);
                float4 av = *reinterpret_cast<const float4*>(&sXT[k][tm * 4]);
                float a[4] = {av.x, av.y, av.z, av.w};
                float bb[4] = {bv.x, bv.y, bv.z, bv.w};
                #pragma unroll
                for (int r = 0; r < 4; r++)
                    #pragma unroll
                    for (int c = 0; c < 4; c++)
                        acc[r][c] = fmaf(a[r], bb[c], acc[r][c]);
            }
            int cbase = tn * 4;
            bool isQ = (cbase >= 64);
            int col = isQ ? (cbase - 64) : cbase;
            float4 bias = make_float4(0.f, 0.f, 0.f, 0.f);
            if (isQ) bias = *reinterpret_cast<const float4*>(b1l + col);
            float* dst = isQ ? g_q1 : g_p1;
            #pragma unroll
            for (int r = 0; r < 4; r++) {
                int node = nodeBase + tm * 4 + r;
                if (node < n) {
                    float4 o;
                    o.x = acc[r][0] + bias.x; o.y = acc[r][1] + bias.y;
                    o.z = acc[r][2] + bias.z; o.w = acc[r][3] + bias.w;
                    *reinterpret_cast<float4*>(dst + (size_t)node * 64 + col) = o;
                }
            }
        }
    }
    gbar(sns);

    // ===== Phase C: CSR scatter =====
    for (int e = gtid; e < E; e += GSZ) {
        int s = ei[(long long)e * m];
        int d = ei[((long long)E + e) * m];
        int pos = atomicAdd(&g_cur[d], 1);
        g_csr[pos] = s;
    }
    gbar(sns);

    // ===== Phase D: agg64 + relu  (warp per node, 8-wide MLP) =====
    {
        int gw = bid * 8 + wid;
        for (int node = gw; node < n; node += NWARPS) {
            int o = g_off[node];
            int d = g_deg[node];
            float ax = 0.f, ay = 0.f;
            int e = 0;
            for (; e + 8 <= d; e += 8) {
                int s0 = __ldg(&g_csr[o + e + 0]);
                int s1 = __ldg(&g_csr[o + e + 1]);
                int s2 = __ldg(&g_csr[o + e + 2]);
                int s3 = __ldg(&g_csr[o + e + 3]);
                int s4 = __ldg(&g_csr[o + e + 4]);
                int s5 = __ldg(&g_csr[o + e + 5]);
                int s6 = __ldg(&g_csr[o + e + 6]);
                int s7 = __ldg(&g_csr[o + e + 7]);
                float2 v0 = __ldg((const float2*)(g_p1 + (size_t)s0 * 64 + lane * 2));
                float2 v1 = __ldg((const float2*)(g_p1 + (size_t)s1 * 64 + lane * 2));
                float2 v2 = __ldg((const float2*)(g_p1 + (size_t)s2 * 64 + lane * 2));
                float2 v3 = __ldg((const float2*)(g_p1 + (size_t)s3 * 64 + lane * 2));
                float2 v4 = __ldg((const float2*)(g_p1 + (size_t)s4 * 64 + lane * 2));
                float2 v5 = __ldg((const float2*)(g_p1 + (size_t)s5 * 64 + lane * 2));
                float2 v6 = __ldg((const float2*)(g_p1 + (size_t)s6 * 64 + lane * 2));
                float2 v7 = __ldg((const float2*)(g_p1 + (size_t)s7 * 64 + lane * 2));
                ax += (v0.x + v1.x) + (v2.x + v3.x) + ((v4.x + v5.x) + (v6.x + v7.x));
                ay += (v0.y + v1.y) + (v2.y + v3.y) + ((v4.y + v5.y) + (v6.y + v7.y));
            }
            for (; e < d; e++) {
                int s0 = __ldg(&g_csr[o + e]);
                float2 v0 = __ldg((const float2*)(g_p1 + (size_t)s0 * 64 + lane * 2));
                ax += v0.x; ay += v0.y;
            }
            float inv = 1.0f / (float)max(d, 1);
            float2 qq = __ldg((const float2*)(g_q1 + (size_t)node * 64 + lane * 2));
            float2 ov;
            ov.x = fmaxf(fmaf(ax, inv, qq.x), 0.0f);
            ov.y = fmaxf(fmaf(ay, inv, qq.y), 0.0f);
            *reinterpret_cast<float2*>(g_h + (size_t)node * 64 + lane * 2) = ov;
        }
    }
    gbar(sns);

    // ===== Phase E: layer-2 dual GEMM (all blocks): p2 = h@W2l, q2 = h@W2r + b2 =====
    {
        float* sW2 = s_pool;                                  // [64][64]
        float (*sXT2)[68] = (float(*)[68])(s_pool + 4096);    // [64][68]
        for (int i = tid; i < 64 * 64; i += NT) {
            int k = i >> 6, c = i & 63;
            sW2[i] = (c < 32) ? W2l[k * 32 + c] : W2r[k * 32 + (c - 32)];
        }
        int ntiles = (n + 63) >> 6;
        for (int t = bid; t < ntiles; t += NB) {
            int nodeBase = t << 6;
            __syncthreads();
            #pragma unroll
            for (int i = 0; i < 4; i++) {
                int flat = tid + i * NT;
                int nd = flat >> 4, k4 = (flat & 15) * 4;
                int node = nodeBase + nd;
                float4 v = make_float4(0.f, 0.f, 0.f, 0.f);
                if (node < n) v = *reinterpret_cast<const float4*>(g_h + (size_t)node * 64 + k4);
                sXT2[k4 + 0][nd] = v.x; sXT2[k4 + 1][nd] = v.y;
                sXT2[k4 + 2][nd] = v.z; sXT2[k4 + 3][nd] = v.w;
            }
            __syncthreads();
            int tn = tid & 15, tm = tid >> 4;
            float acc[4][4];
            #pragma unroll
            for (int r = 0; r < 4; r++)
                #pragma unroll
                for (int c = 0; c < 4; c++) acc[r][c] = 0.0f;
            #pragma unroll 8
            for (int k = 0; k < 64; k++) {
                float4 bv = *reinterpret_cast<const float4*>(&sW2[k * 64 + tn * 4]);
                float4 av = *reinterpret_cast<const float4*>(&sXT2[k][tm * 4]);
                float a[4] = {av.x, av.y, av.z, av.w};
                float bb[4] = {bv.x, bv.y, bv.z, bv.w};
                #pragma unroll
                for (int r = 0; r < 4; r++)
                    #pragma unroll
                    for (int c = 0; c < 4; c++)
                        acc[r][c] = fmaf(a[r], bb[c], acc[r][c]);
            }
            int cbase = tn * 4;
            bool isQ = (cbase >= 32);
            int col = isQ ? (cbase - 32) : cbase;
            float4 bias = make_float4(0.f, 0.f, 0.f, 0.f);
            if (isQ) bias = *reinterpret_cast<const float4*>(b2l + col);
            float* dst = isQ ? g_q2 : g_p2;
            #pragma unroll
            for (int r = 0; r < 4; r++) {
                int node = nodeBase + tm * 4 + r;
                if (node < n) {
                    float4 o;
                    o.x = acc[r][0] + bias.x; o.y = acc[r][1] + bias.y;
                    o.z = acc[r][2] + bias.z; o.w = acc[r][3] + bias.w;
                    *reinterpret_cast<float4*>(dst + (size_t)node * 32 + col) = o;
                }
            }
        }
    }
    gbar(sns);

    // ===== Phase F: agg32 -> out, restore deg==0 invariant =====
    {
        int gw = bid * 8 + wid;
        for (int node = gw; node < n; node += NWARPS) {
            int o = g_off[node];
            int d = g_deg[node];
            if (lane == 0) g_deg[node] = 0;
            float a = 0.f;
            int e = 0;
            for (; e + 8 <= d; e += 8) {
                int s0 = __ldg(&g_csr[o + e + 0]);
                int s1 = __ldg(&g_csr[o + e + 1]);
                int s2 = __ldg(&g_csr[o + e + 2]);
                int s3 = __ldg(&g_csr[o + e + 3]);
                int s4 = __ldg(&g_csr[o + e + 4]);
                int s5 = __ldg(&g_csr[o + e + 5]);
                int s6 = __ldg(&g_csr[o + e + 6]);
                int s7 = __ldg(&g_csr[o + e + 7]);
                float v0 = __ldg(g_p2 + (size_t)s0 * 32 + lane);
                float v1 = __ldg(g_p2 + (size_t)s1 * 32 + lane);
                float v2 = __ldg(g_p2 + (size_t)s2 * 32 + lane);
                float v3 = __ldg(g_p2 + (size_t)s3 * 32 + lane);
                float v4 = __ldg(g_p2 + (size_t)s4 * 32 + lane);
                float v5 = __ldg(g_p2 + (size_t)s5 * 32 + lane);
                float v6 = __ldg(g_p2 + (size_t)s6 * 32 + lane);
                float v7 = __ldg(g_p2 + (size_t)s7 * 32 + lane);
                a += (v0 + v1) + (v2 + v3) + ((v4 + v5) + (v6 + v7));
            }
            for (; e < d; e++) {
                int s0 = __ldg(&g_csr[o + e]);
                a += __ldg(g_p2 + (size_t)s0 * 32 + lane);
            }
            float inv = 1.0f / (float)max(d, 1);
            out[(size_t)node * 32 + lane] = fmaf(a, inv, __ldg(g_q2 + (size_t)node * 32 + lane));
        }
    }
}

// ---------------- launcher: ONE kernel ----------------
extern "C" void kernel_launch(void* const* d_in, const int* in_sizes, int n_in,
                              void* d_out, int out_size)
{
    const float* x   = (const float*)d_in[0];
    const int*   ei  = (const int*)d_in[1];
    const float* W1l = (const float*)d_in[2];
    const float* b1l = (const float*)d_in[3];
    const float* W1r = (const float*)d_in[4];
    const float* W2l = (const float*)d_in[5];
    const float* b2l = (const float*)d_in[6];
    const float* W2r = (const float*)d_in[7];
    float* out = (float*)d_out;

    int n = in_sizes[0] / 64;      // 100000
    int E = in_sizes[1] / 2;       // 1600000

    k_mono<<<NB, NT>>>(ei, x, W1l, b1l, W1r, W2l, b2l, W2r, out, n, E);
}

// round 7
// speedup vs baseline: 12.2625x; 1.0838x over previous
#include <cuda_runtime.h>

#define NMAX   100000
#define EMAX   1600000
#define NB     444            // 3 blocks/SM on 148 SMs -> guaranteed co-resident
#define NT     256
#define GSZ    (NB * NT)
#define NWARPS (NB * 8)

// ---------------- persistent state (no allocations allowed) ----------------
// INVARIANT: g_deg all-zero at entry (BSS-zero first run; re-zeroed in last phase).
__device__ int g_bar_count;   // barrier arrival counter (returns to 0 after each barrier)
__device__ int g_bar_sense;   // barrier sense (persists; re-read at kernel start)
__device__ int g_deg[NMAX];
__device__ int g_off[NMAX];
__device__ int g_cur[NMAX];
__device__ int g_csr[EMAX];
__device__ __align__(16) float g_p1[NMAX * 64];
__device__ __align__(16) float g_q1[NMAX * 64];
__device__ __align__(16) float g_h [NMAX * 64];
__device__ __align__(16) float g_p2[NMAX * 32];
__device__ __align__(16) float g_q2[NMAX * 32];

// ---------------- grid-wide barrier (sense reversal, co-resident grid) ----------------
__device__ __forceinline__ void gbar(int& sns) {
    __syncthreads();
    if (threadIdx.x == 0) {
        sns ^= 1;
        __threadfence();
        if (atomicAdd(&g_bar_count, 1) == NB - 1) {
            atomicExch(&g_bar_count, 0);
            __threadfence();
            atomicExch(&g_bar_sense, sns);
        } else {
            while (atomicAdd(&g_bar_sense, 0) != sns) __nanosleep(64);
        }
        __threadfence();
    }
    __syncthreads();
}

// ---------------- the whole model in one launch ----------------
__global__ __launch_bounds__(NT, 3) void k_mono(
    const int* __restrict__ ei, const float* __restrict__ x,
    const float* __restrict__ W1l, const float* __restrict__ b1l,
    const float* __restrict__ W1r, const float* __restrict__ W2l,
    const float* __restrict__ b2l, const float* __restrict__ W2r,
    float* __restrict__ out, int n, int E)
{
    __shared__ __align__(16) float s_pool[10496];   // 41,984 B: gemm smem (reused)
    __shared__ int s_wsum[8];
    __shared__ int s_m;

    const int tid  = threadIdx.x;
    const int bid  = blockIdx.x;
    const int gtid = bid * NT + tid;
    const int lane = tid & 31;
    const int wid  = tid >> 5;

    // dtype detect: int64 LE values <1e5 -> all odd 32-bit words are 0
    if (tid == 0) {
        int orv = 0;
        #pragma unroll
        for (int k = 0; k < 64; k++) orv |= ei[2 * k + 1];
        s_m = (orv == 0) ? 2 : 1;
    }
    __syncthreads();
    const int m = s_m;

    int sns = 0;
    if (tid == 0) sns = g_bar_sense;

    // ===== Phase A: degree count (relies on deg==0 invariant) =====
    for (int e = gtid; e < E; e += GSZ) {
        int d = ei[((long long)E + e) * m];
        atomicAdd(&g_deg[d], 1);
    }
    gbar(sns);

    // ===== Phase B: block0 scans; blocks 1..NB-1 do layer-1 dual GEMM =====
    if (bid == 0) {
        int carry = 0;
        int nch = (n + 1023) >> 10;
        for (int c = 0; c < nch; c++) {
            int base = (c << 10) + tid * 4;
            int4 v4 = make_int4(0, 0, 0, 0);
            if (base + 3 < n) v4 = *reinterpret_cast<const int4*>(g_deg + base);
            else {
                if (base     < n) v4.x = g_deg[base];
                if (base + 1 < n) v4.y = g_deg[base + 1];
                if (base + 2 < n) v4.z = g_deg[base + 2];
            }
            int s0 = v4.x, s1 = s0 + v4.y, s2 = s1 + v4.z, s3 = s2 + v4.w;
            int v = s3;
            #pragma unroll
            for (int d = 1; d < 32; d <<= 1) {
                int t = __shfl_up_sync(0xffffffffu, v, d);
                if (lane >= d) v += t;
            }
            if (lane == 31) s_wsum[wid] = v;
            __syncthreads();
            if (tid < 8) {
                int w = s_wsum[tid];
                #pragma unroll
                for (int d = 1; d < 8; d <<= 1) {
                    int t = __shfl_up_sync(0xffu, w, d, 8);
                    if (tid >= d) w += t;
                }
                s_wsum[tid] = w;
            }
            __syncthreads();
            int pre = carry + (wid ? s_wsum[wid - 1] : 0) + (v - s3);
            if (base     < n) { g_off[base]     = pre;      g_cur[base]     = pre;      }
            if (base + 1 < n) { g_off[base + 1] = pre + s0; g_cur[base + 1] = pre + s0; }
            if (base + 2 < n) { g_off[base + 2] = pre + s1; g_cur[base + 2] = pre + s1; }
            if (base + 3 < n) { g_off[base + 3] = pre + s2; g_cur[base + 3] = pre + s2; }
            int tot = s_wsum[7];
            __syncthreads();
            carry += tot;
        }
    } else {
        // gemm64: p1 = x@W1l, q1 = x@W1r + b1; MT=32 nodes/tile, NC=128 cols
        float* sW = s_pool;                                   // [64][128]
        float (*sXT)[36] = (float(*)[36])(s_pool + 8192);     // [64][36]
        for (int i = tid; i < 64 * 128; i += NT) {
            int k = i >> 7, c = i & 127;
            sW[i] = (c < 64) ? W1l[k * 64 + c] : W1r[k * 64 + (c - 64)];
        }
        int ntiles = (n + 31) >> 5;
        for (int t = bid - 1; t < ntiles; t += NB - 1) {
            int nodeBase = t << 5;
            __syncthreads();
            #pragma unroll
            for (int i = 0; i < 2; i++) {
                int flat = tid + i * NT;
                int nd = flat >> 4, k4 = (flat & 15) * 4;
                int node = nodeBase + nd;
                float4 v = make_float4(0.f, 0.f, 0.f, 0.f);
                if (node < n) v = *reinterpret_cast<const float4*>(x + (size_t)node * 64 + k4);
                sXT[k4 + 0][nd] = v.x; sXT[k4 + 1][nd] = v.y;
                sXT[k4 + 2][nd] = v.z; sXT[k4 + 3][nd] = v.w;
            }
            __syncthreads();
            int tn = tid & 31, tm = tid >> 5;
            float acc[4][4];
            #pragma unroll
            for (int r = 0; r < 4; r++)
                #pragma unroll
                for (int c = 0; c < 4; c++) acc[r][c] = 0.0f;
            #pragma unroll 8
            for (int k = 0; k < 64; k++) {
                float4 bv = *reinterpret_cast<const float4*>(&sW[k * 128 + tn * 4]);
                float4 av = *reinterpret_cast<const float4*>(&sXT[k][tm * 4]);
                float a[4] = {av.x, av.y, av.z, av.w};
                float bb[4] = {bv.x, bv.y, bv.z, bv.w};
                #pragma unroll
                for (int r = 0; r < 4; r++)
                    #pragma unroll
                    for (int c = 0; c < 4; c++)
                        acc[r][c] = fmaf(a[r], bb[c], acc[r][c]);
            }
            int cbase = tn * 4;
            bool isQ = (cbase >= 64);
            int col = isQ ? (cbase - 64) : cbase;
            float4 bias = make_float4(0.f, 0.f, 0.f, 0.f);
            if (isQ) bias = *reinterpret_cast<const float4*>(b1l + col);
            float* dst = isQ ? g_q1 : g_p1;
            #pragma unroll
            for (int r = 0; r < 4; r++) {
                int node = nodeBase + tm * 4 + r;
                if (node < n) {
                    float4 o;
                    o.x = acc[r][0] + bias.x; o.y = acc[r][1] + bias.y;
                    o.z = acc[r][2] + bias.z; o.w = acc[r][3] + bias.w;
                    *reinterpret_cast<float4*>(dst + (size_t)node * 64 + col) = o;
                }
            }
        }
    }
    gbar(sns);

    // ===== Phase C: CSR scatter =====
    for (int e = gtid; e < E; e += GSZ) {
        int s = ei[(long long)e * m];
        int d = ei[((long long)E + e) * m];
        int pos = atomicAdd(&g_cur[d], 1);
        g_csr[pos] = s;
    }
    gbar(sns);

    // ===== Phase D: agg64 + relu  (warp per node, 8-wide MLP) =====
    {
        int gw = bid * 8 + wid;
        for (int node = gw; node < n; node += NWARPS) {
            int o = g_off[node];
            int d = g_deg[node];
            float ax = 0.f, ay = 0.f;
            int e = 0;
            for (; e + 8 <= d; e += 8) {
                int s0 = __ldg(&g_csr[o + e + 0]);
                int s1 = __ldg(&g_csr[o + e + 1]);
                int s2 = __ldg(&g_csr[o + e + 2]);
                int s3 = __ldg(&g_csr[o + e + 3]);
                int s4 = __ldg(&g_csr[o + e + 4]);
                int s5 = __ldg(&g_csr[o + e + 5]);
                int s6 = __ldg(&g_csr[o + e + 6]);
                int s7 = __ldg(&g_csr[o + e + 7]);
                float2 v0 = __ldg((const float2*)(g_p1 + (size_t)s0 * 64 + lane * 2));
                float2 v1 = __ldg((const float2*)(g_p1 + (size_t)s1 * 64 + lane * 2));
                float2 v2 = __ldg((const float2*)(g_p1 + (size_t)s2 * 64 + lane * 2));
                float2 v3 = __ldg((const float2*)(g_p1 + (size_t)s3 * 64 + lane * 2));
                float2 v4 = __ldg((const float2*)(g_p1 + (size_t)s4 * 64 + lane * 2));
                float2 v5 = __ldg((const float2*)(g_p1 + (size_t)s5 * 64 + lane * 2));
                float2 v6 = __ldg((const float2*)(g_p1 + (size_t)s6 * 64 + lane * 2));
                float2 v7 = __ldg((const float2*)(g_p1 + (size_t)s7 * 64 + lane * 2));
                ax += (v0.x + v1.x) + (v2.x + v3.x) + ((v4.x + v5.x) + (v6.x + v7.x));
                ay += (v0.y + v1.y) + (v2.y + v3.y) + ((v4.y + v5.y) + (v6.y + v7.y));
            }
            for (; e < d; e++) {
                int s0 = __ldg(&g_csr[o + e]);
                float2 v0 = __ldg((const float2*)(g_p1 + (size_t)s0 * 64 + lane * 2));
                ax += v0.x; ay += v0.y;
            }
            float inv = 1.0f / (float)max(d, 1);
            float2 qq = __ldg((const float2*)(g_q1 + (size_t)node * 64 + lane * 2));
            float2 ov;
            ov.x = fmaxf(fmaf(ax, inv, qq.x), 0.0f);
            ov.y = fmaxf(fmaf(ay, inv, qq.y), 0.0f);
            *reinterpret_cast<float2*>(g_h + (size_t)node * 64 + lane * 2) = ov;
        }
    }
    gbar(sns);

    // ===== Phase E: layer-2 dual GEMM (all blocks): p2 = h@W2l, q2 = h@W2r + b2 =====
    {
        float* sW2 = s_pool;                                  // [64][64]
        float (*sXT2)[68] = (float(*)[68])(s_pool + 4096);    // [64][68]
        for (int i = tid; i < 64 * 64; i += NT) {
            int k = i >> 6, c = i & 63;
            sW2[i] = (c < 32) ? W2l[k * 32 + c] : W2r[k * 32 + (c - 32)];
        }
        int ntiles = (n + 63) >> 6;
        for (int t = bid; t < ntiles; t += NB) {
            int nodeBase = t << 6;
            __syncthreads();
            #pragma unroll
            for (int i = 0; i < 4; i++) {
                int flat = tid + i * NT;
                int nd = flat >> 4, k4 = (flat & 15) * 4;
                int node = nodeBase + nd;
                float4 v = make_float4(0.f, 0.f, 0.f, 0.f);
                if (node < n) v = *reinterpret_cast<const float4*>(g_h + (size_t)node * 64 + k4);
                sXT2[k4 + 0][nd] = v.x; sXT2[k4 + 1][nd] = v.y;
                sXT2[k4 + 2][nd] = v.z; sXT2[k4 + 3][nd] = v.w;
            }
            __syncthreads();
            int tn = tid & 15, tm = tid >> 4;
            float acc[4][4];
            #pragma unroll
            for (int r = 0; r < 4; r++)
                #pragma unroll
                for (int c = 0; c < 4; c++) acc[r][c] = 0.0f;
            #pragma unroll 8
            for (int k = 0; k < 64; k++) {
                float4 bv = *reinterpret_cast<const float4*>(&sW2[k * 64 + tn * 4]);
                float4 av = *reinterpret_cast<const float4*>(&sXT2[k][tm * 4]);
                float a[4] = {av.x, av.y, av.z, av.w};
                float bb[4] = {bv.x, bv.y, bv.z, bv.w};
                #pragma unroll
                for (int r = 0; r < 4; r++)
                    #pragma unroll
                    for (int c = 0; c < 4; c++)
                        acc[r][c] = fmaf(a[r], bb[c], acc[r][c]);
            }
            int cbase = tn * 4;
            bool isQ = (cbase >= 32);
            int col = isQ ? (cbase - 32) : cbase;
            float4 bias = make_float4(0.f, 0.f, 0.f, 0.f);
            if (isQ) bias = *reinterpret_cast<const float4*>(b2l + col);
            float* dst = isQ ? g_q2 : g_p2;
            #pragma unroll
            for (int r = 0; r < 4; r++) {
                int node = nodeBase + tm * 4 + r;
                if (node < n) {
                    float4 o;
                    o.x = acc[r][0] + bias.x; o.y = acc[r][1] + bias.y;
                    o.z = acc[r][2] + bias.z; o.w = acc[r][3] + bias.w;
                    *reinterpret_cast<float4*>(dst + (size_t)node * 32 + col) = o;
                }
            }
        }
    }
    gbar(sns);

    // ===== Phase F: agg32 -> out, restore deg==0 invariant =====
    {
        int gw = bid * 8 + wid;
        for (int node = gw; node < n; node += NWARPS) {
            int o = g_off[node];
            int d = g_deg[node];
            if (lane == 0) g_deg[node] = 0;
            float a = 0.f;
            int e = 0;
            for (; e + 8 <= d; e += 8) {
                int s0 = __ldg(&g_csr[o + e + 0]);
                int s1 = __ldg(&g_csr[o + e + 1]);
                int s2 = __ldg(&g_csr[o + e + 2]);
                int s3 = __ldg(&g_csr[o + e + 3]);
                int s4 = __ldg(&g_csr[o + e + 4]);
                int s5 = __ldg(&g_csr[o + e + 5]);
                int s6 = __ldg(&g_csr[o + e + 6]);
                int s7 = __ldg(&g_csr[o + e + 7]);
                float v0 = __ldg(g_p2 + (size_t)s0 * 32 + lane);
                float v1 = __ldg(g_p2 + (size_t)s1 * 32 + lane);
                float v2 = __ldg(g_p2 + (size_t)s2 * 32 + lane);
                float v3 = __ldg(g_p2 + (size_t)s3 * 32 + lane);
                float v4 = __ldg(g_p2 + (size_t)s4 * 32 + lane);
                float v5 = __ldg(g_p2 + (size_t)s5 * 32 + lane);
                float v6 = __ldg(g_p2 + (size_t)s6 * 32 + lane);
                float v7 = __ldg(g_p2 + (size_t)s7 * 32 + lane);
                a += (v0 + v1) + (v2 + v3) + ((v4 + v5) + (v6 + v7));
            }
            for (; e < d; e++) {
                int s0 = __ldg(&g_csr[o + e]);
                a += __ldg(g_p2 + (size_t)s0 * 32 + lane);
            }
            float inv = 1.0f / (float)max(d, 1);
            out[(size_t)node * 32 + lane] = fmaf(a, inv, __ldg(g_q2 + (size_t)node * 32 + lane));
        }
    }
}

// ---------------- launcher: ONE kernel ----------------
extern "C" void kernel_launch(void* const* d_in, const int* in_sizes, int n_in,
                              void* d_out, int out_size)
{
    const float* x   = (const float*)d_in[0];
    const int*   ei  = (const int*)d_in[1];
    const float* W1l = (const float*)d_in[2];
    const float* b1l = (const float*)d_in[3];
    const float* W1r = (const float*)d_in[4];
    const float* W2l = (const float*)d_in[5];
    const float* b2l = (const float*)d_in[6];
    const float* W2r = (const float*)d_in[7];
    float* out = (float*)d_out;

    int n = in_sizes[0] / 64;      // 100000
    int E = in_sizes[1] / 2;       // 1600000

    k_mono<<<NB, NT>>>(ei, x, W1l, b1l, W1r, W2l, b2l, W2r, out, n, E);
}

// round 8
// speedup vs baseline: 13.1257x; 1.0704x over previous
#include <cuda_runtime.h>

#define NMAX   100000
#define EMAX   1600000
#define NB     592            // 4 blocks/SM on 148 SMs -> guaranteed co-resident
#define NT     256
#define GSZ    (NB * NT)
#define NWARPS (NB * 8)

// ---------------- persistent state (no allocations allowed) ----------------
// INVARIANT: g_deg all-zero at entry (BSS-zero first run; re-zeroed in last phase).
__device__ int g_bar_count;   // barrier arrival counter (returns to 0 after each barrier)
__device__ int g_bar_sense;   // barrier sense (persists; re-read at kernel start)
__device__ int g_deg[NMAX];
__device__ int g_off[NMAX];
__device__ int g_cur[NMAX];
__device__ int g_csr[EMAX];
__device__ __align__(16) float g_p1[NMAX * 64];
__device__ __align__(16) float g_q1[NMAX * 64];
__device__ __align__(16) float g_h [NMAX * 64];
__device__ __align__(16) float g_p2[NMAX * 32];
__device__ __align__(16) float g_q2[NMAX * 32];

// ---------------- grid-wide barrier (sense reversal, volatile-load spin) ----------------
__device__ __forceinline__ void gbar(int& sns) {
    __syncthreads();
    if (threadIdx.x == 0) {
        sns ^= 1;
        __threadfence();
        if (atomicAdd(&g_bar_count, 1) == NB - 1) {
            atomicExch(&g_bar_count, 0);
            __threadfence();
            *(volatile int*)&g_bar_sense = sns;       // release: one store
        } else {
            while (*(volatile int*)&g_bar_sense != sns) __nanosleep(32);  // load spin (no atomic serialization)
        }
        __threadfence();
    }
    __syncthreads();
}

// ---------------- the whole model in one launch ----------------
__global__ __launch_bounds__(NT, 4) void k_mono(
    const int* __restrict__ ei, const float* __restrict__ x,
    const float* __restrict__ W1l, const float* __restrict__ b1l,
    const float* __restrict__ W1r, const float* __restrict__ W2l,
    const float* __restrict__ b2l, const float* __restrict__ W2r,
    float* __restrict__ out, int n, int E)
{
    __shared__ __align__(16) float s_pool[10496];   // 41,984 B: gemm smem (reused)
    __shared__ int s_wsum[8];
    __shared__ int s_m;

    const int tid  = threadIdx.x;
    const int bid  = blockIdx.x;
    const int gtid = bid * NT + tid;
    const int lane = tid & 31;
    const int wid  = tid >> 5;

    // dtype detect: int64 LE values <1e5 -> all odd 32-bit words are 0
    if (tid == 0) {
        int orv = 0;
        #pragma unroll
        for (int k = 0; k < 64; k++) orv |= ei[2 * k + 1];
        s_m = (orv == 0) ? 2 : 1;
    }
    __syncthreads();
    const int m = s_m;

    int sns = 0;
    if (tid == 0) sns = *(volatile int*)&g_bar_sense;

    // ===== Phase A: degree count (relies on deg==0 invariant) =====
    for (int e = gtid; e < E; e += GSZ) {
        int d = ei[((long long)E + e) * m];
        atomicAdd(&g_deg[d], 1);
    }
    gbar(sns);

    // ===== Phase B: block0 scans; blocks 1..NB-1 do layer-1 dual GEMM =====
    if (bid == 0) {
        int carry = 0;
        int nch = (n + 1023) >> 10;
        for (int c = 0; c < nch; c++) {
            int base = (c << 10) + tid * 4;
            int4 v4 = make_int4(0, 0, 0, 0);
            if (base + 3 < n) v4 = *reinterpret_cast<const int4*>(g_deg + base);
            else {
                if (base     < n) v4.x = g_deg[base];
                if (base + 1 < n) v4.y = g_deg[base + 1];
                if (base + 2 < n) v4.z = g_deg[base + 2];
            }
            int s0 = v4.x, s1 = s0 + v4.y, s2 = s1 + v4.z, s3 = s2 + v4.w;
            int v = s3;
            #pragma unroll
            for (int d = 1; d < 32; d <<= 1) {
                int t = __shfl_up_sync(0xffffffffu, v, d);
                if (lane >= d) v += t;
            }
            if (lane == 31) s_wsum[wid] = v;
            __syncthreads();
            if (tid < 8) {
                int w = s_wsum[tid];
                #pragma unroll
                for (int d = 1; d < 8; d <<= 1) {
                    int t = __shfl_up_sync(0xffu, w, d, 8);
                    if (tid >= d) w += t;
                }
                s_wsum[tid] = w;
            }
            __syncthreads();
            int pre = carry + (wid ? s_wsum[wid - 1] : 0) + (v - s3);
            if (base     < n) { g_off[base]     = pre;      g_cur[base]     = pre;      }
            if (base + 1 < n) { g_off[base + 1] = pre + s0; g_cur[base + 1] = pre + s0; }
            if (base + 2 < n) { g_off[base + 2] = pre + s1; g_cur[base + 2] = pre + s1; }
            if (base + 3 < n) { g_off[base + 3] = pre + s2; g_cur[base + 3] = pre + s2; }
            int tot = s_wsum[7];
            __syncthreads();
            carry += tot;
        }
    } else {
        // gemm64: p1 = x@W1l, q1 = x@W1r + b1; MT=32 nodes/tile, NC=128 cols
        float* sW = s_pool;                                   // [64][128]
        float (*sXT)[36] = (float(*)[36])(s_pool + 8192);     // [64][36]
        for (int i = tid; i < 64 * 128; i += NT) {
            int k = i >> 7, c = i & 127;
            sW[i] = (c < 64) ? W1l[k * 64 + c] : W1r[k * 64 + (c - 64)];
        }
        int ntiles = (n + 31) >> 5;
        for (int t = bid - 1; t < ntiles; t += NB - 1) {
            int nodeBase = t << 5;
            __syncthreads();
            #pragma unroll
            for (int i = 0; i < 2; i++) {
                int flat = tid + i * NT;
                int nd = flat >> 4, k4 = (flat & 15) * 4;
                int node = nodeBase + nd;
                float4 v = make_float4(0.f, 0.f, 0.f, 0.f);
                if (node < n) v = *reinterpret_cast<const float4*>(x + (size_t)node * 64 + k4);
                sXT[k4 + 0][nd] = v.x; sXT[k4 + 1][nd] = v.y;
                sXT[k4 + 2][nd] = v.z; sXT[k4 + 3][nd] = v.w;
            }
            __syncthreads();
            int tn = tid & 31, tm = tid >> 5;
            float acc[4][4];
            #pragma unroll
            for (int r = 0; r < 4; r++)
                #pragma unroll
                for (int c = 0; c < 4; c++) acc[r][c] = 0.0f;
            #pragma unroll 8
            for (int k = 0; k < 64; k++) {
                float4 bv = *reinterpret_cast<const float4*>(&sW[k * 128 + tn * 4]);
                float4 av = *reinterpret_cast<const float4*>(&sXT[k][tm * 4]);
                float a[4] = {av.x, av.y, av.z, av.w};
                float bb[4] = {bv.x, bv.y, bv.z, bv.w};
                #pragma unroll
                for (int r = 0; r < 4; r++)
                    #pragma unroll
                    for (int c = 0; c < 4; c++)
                        acc[r][c] = fmaf(a[r], bb[c], acc[r][c]);
            }
            int cbase = tn * 4;
            bool isQ = (cbase >= 64);
            int col = isQ ? (cbase - 64) : cbase;
            float4 bias = make_float4(0.f, 0.f, 0.f, 0.f);
            if (isQ) bias = *reinterpret_cast<const float4*>(b1l + col);
            float* dst = isQ ? g_q1 : g_p1;
            #pragma unroll
            for (int r = 0; r < 4; r++) {
                int node = nodeBase + tm * 4 + r;
                if (node < n) {
                    float4 o;
                    o.x = acc[r][0] + bias.x; o.y = acc[r][1] + bias.y;
                    o.z = acc[r][2] + bias.z; o.w = acc[r][3] + bias.w;
                    *reinterpret_cast<float4*>(dst + (size_t)node * 64 + col) = o;
                }
            }
        }
    }
    gbar(sns);

    // ===== Phase C: CSR scatter =====
    for (int e = gtid; e < E; e += GSZ) {
        int s = ei[(long long)e * m];
        int d = ei[((long long)E + e) * m];
        int pos = atomicAdd(&g_cur[d], 1);
        g_csr[pos] = s;
    }
    gbar(sns);

    // ===== Phase D: agg64 + relu  (warp per node, 8-wide MLP) =====
    {
        int gw = bid * 8 + wid;
        for (int node = gw; node < n; node += NWARPS) {
            int o = g_off[node];
            int d = g_deg[node];
            float ax = 0.f, ay = 0.f;
            int e = 0;
            for (; e + 8 <= d; e += 8) {
                int s0 = __ldg(&g_csr[o + e + 0]);
                int s1 = __ldg(&g_csr[o + e + 1]);
                int s2 = __ldg(&g_csr[o + e + 2]);
                int s3 = __ldg(&g_csr[o + e + 3]);
                int s4 = __ldg(&g_csr[o + e + 4]);
                int s5 = __ldg(&g_csr[o + e + 5]);
                int s6 = __ldg(&g_csr[o + e + 6]);
                int s7 = __ldg(&g_csr[o + e + 7]);
                float2 v0 = __ldg((const float2*)(g_p1 + (size_t)s0 * 64 + lane * 2));
                float2 v1 = __ldg((const float2*)(g_p1 + (size_t)s1 * 64 + lane * 2));
                float2 v2 = __ldg((const float2*)(g_p1 + (size_t)s2 * 64 + lane * 2));
                float2 v3 = __ldg((const float2*)(g_p1 + (size_t)s3 * 64 + lane * 2));
                float2 v4 = __ldg((const float2*)(g_p1 + (size_t)s4 * 64 + lane * 2));
                float2 v5 = __ldg((const float2*)(g_p1 + (size_t)s5 * 64 + lane * 2));
                float2 v6 = __ldg((const float2*)(g_p1 + (size_t)s6 * 64 + lane * 2));
                float2 v7 = __ldg((const float2*)(g_p1 + (size_t)s7 * 64 + lane * 2));
                ax += (v0.x + v1.x) + (v2.x + v3.x) + ((v4.x + v5.x) + (v6.x + v7.x));
                ay += (v0.y + v1.y) + (v2.y + v3.y) + ((v4.y + v5.y) + (v6.y + v7.y));
            }
            for (; e < d; e++) {
                int s0 = __ldg(&g_csr[o + e]);
                float2 v0 = __ldg((const float2*)(g_p1 + (size_t)s0 * 64 + lane * 2));
                ax += v0.x; ay += v0.y;
            }
            float inv = 1.0f / (float)max(d, 1);
            float2 qq = __ldg((const float2*)(g_q1 + (size_t)node * 64 + lane * 2));
            float2 ov;
            ov.x = fmaxf(fmaf(ax, inv, qq.x), 0.0f);
            ov.y = fmaxf(fmaf(ay, inv, qq.y), 0.0f);
            *reinterpret_cast<float2*>(g_h + (size_t)node * 64 + lane * 2) = ov;
        }
    }
    gbar(sns);

    // ===== Phase E: layer-2 dual GEMM (all blocks): p2 = h@W2l, q2 = h@W2r + b2 =====
    {
        float* sW2 = s_pool;                                  // [64][64]
        float (*sXT2)[68] = (float(*)[68])(s_pool + 4096);    // [64][68]
        for (int i = tid; i < 64 * 64; i += NT) {
            int k = i >> 6, c = i & 63;
            sW2[i] = (c < 32) ? W2l[k * 32 + c] : W2r[k * 32 + (c - 32)];
        }
        int ntiles = (n + 63) >> 6;
        for (int t = bid; t < ntiles; t += NB) {
            int nodeBase = t << 6;
            __syncthreads();
            #pragma unroll
            for (int i = 0; i < 4; i++) {
                int flat = tid + i * NT;
                int nd = flat >> 4, k4 = (flat & 15) * 4;
                int node = nodeBase + nd;
                float4 v = make_float4(0.f, 0.f, 0.f, 0.f);
                if (node < n) v = *reinterpret_cast<const float4*>(g_h + (size_t)node * 64 + k4);
                sXT2[k4 + 0][nd] = v.x; sXT2[k4 + 1][nd] = v.y;
                sXT2[k4 + 2][nd] = v.z; sXT2[k4 + 3][nd] = v.w;
            }
            __syncthreads();
            int tn = tid & 15, tm = tid >> 4;
            float acc[4][4];
            #pragma unroll
            for (int r = 0; r < 4; r++)
                #pragma unroll
                for (int c = 0; c < 4; c++) acc[r][c] = 0.0f;
            #pragma unroll 8
            for (int k = 0; k < 64; k++) {
                float4 bv = *reinterpret_cast<const float4*>(&sW2[k * 64 + tn * 4]);
                float4 av = *reinterpret_cast<const float4*>(&sXT2[k][tm * 4]);
                float a[4] = {av.x, av.y, av.z, av.w};
                float bb[4] = {bv.x, bv.y, bv.z, bv.w};
                #pragma unroll
                for (int r = 0; r < 4; r++)
                    #pragma unroll
                    for (int c = 0; c < 4; c++)
                        acc[r][c] = fmaf(a[r], bb[c], acc[r][c]);
            }
            int cbase = tn * 4;
            bool isQ = (cbase >= 32);
            int col = isQ ? (cbase - 32) : cbase;
            float4 bias = make_float4(0.f, 0.f, 0.f, 0.f);
            if (isQ) bias = *reinterpret_cast<const float4*>(b2l + col);
            float* dst = isQ ? g_q2 : g_p2;
            #pragma unroll
            for (int r = 0; r < 4; r++) {
                int node = nodeBase + tm * 4 + r;
                if (node < n) {
                    float4 o;
                    o.x = acc[r][0] + bias.x; o.y = acc[r][1] + bias.y;
                    o.z = acc[r][2] + bias.z; o.w = acc[r][3] + bias.w;
                    *reinterpret_cast<float4*>(dst + (size_t)node * 32 + col) = o;
                }
            }
        }
    }
    gbar(sns);

    // ===== Phase F: agg32 -> out, restore deg==0 invariant =====
    {
        int gw = bid * 8 + wid;
        for (int node = gw; node < n; node += NWARPS) {
            int o = g_off[node];
            int d = g_deg[node];
            if (lane == 0) g_deg[node] = 0;
            float a = 0.f;
            int e = 0;
            for (; e + 8 <= d; e += 8) {
                int s0 = __ldg(&g_csr[o + e + 0]);
                int s1 = __ldg(&g_csr[o + e + 1]);
                int s2 = __ldg(&g_csr[o + e + 2]);
                int s3 = __ldg(&g_csr[o + e + 3]);
                int s4 = __ldg(&g_csr[o + e + 4]);
                int s5 = __ldg(&g_csr[o + e + 5]);
                int s6 = __ldg(&g_csr[o + e + 6]);
                int s7 = __ldg(&g_csr[o + e + 7]);
                float v0 = __ldg(g_p2 + (size_t)s0 * 32 + lane);
                float v1 = __ldg(g_p2 + (size_t)s1 * 32 + lane);
                float v2 = __ldg(g_p2 + (size_t)s2 * 32 + lane);
                float v3 = __ldg(g_p2 + (size_t)s3 * 32 + lane);
                float v4 = __ldg(g_p2 + (size_t)s4 * 32 + lane);
                float v5 = __ldg(g_p2 + (size_t)s5 * 32 + lane);
                float v6 = __ldg(g_p2 + (size_t)s6 * 32 + lane);
                float v7 = __ldg(g_p2 + (size_t)s7 * 32 + lane);
                a += (v0 + v1) + (v2 + v3) + ((v4 + v5) + (v6 + v7));
            }
            for (; e < d; e++) {
                int s0 = __ldg(&g_csr[o + e]);
                a += __ldg(g_p2 + (size_t)s0 * 32 + lane);
            }
            float inv = 1.0f / (float)max(d, 1);
            out[(size_t)node * 32 + lane] = fmaf(a, inv, __ldg(g_q2 + (size_t)node * 32 + lane));
        }
    }
}

// ---------------- launcher: ONE kernel ----------------
extern "C" void kernel_launch(void* const* d_in, const int* in_sizes, int n_in,
                              void* d_out, int out_size)
{
    const float* x   = (const float*)d_in[0];
    const int*   ei  = (const int*)d_in[1];
    const float* W1l = (const float*)d_in[2];
    const float* b1l = (const float*)d_in[3];
    const float* W1r = (const float*)d_in[4];
    const float* W2l = (const float*)d_in[5];
    const float* b2l = (const float*)d_in[6];
    const float* W2r = (const float*)d_in[7];
    float* out = (float*)d_out;

    int n = in_sizes[0] / 64;      // 100000
    int E = in_sizes[1] / 2;       // 1600000

    k_mono<<<NB, NT>>>(ei, x, W1l, b1l, W1r, W2l, b2l, W2r, out, n, E);
}

// round 9
// speedup vs baseline: 13.4910x; 1.0278x over previous
#include <cuda_runtime.h>

#define NMAX   100000
#define EMAX   1600000
#define NB     592            // 4 blocks/SM on 148 SMs -> guaranteed co-resident
#define NT     256
#define GSZ    (NB * NT)
#define NWARPS (NB * 8)

typedef unsigned long long ull;

// ---------------- f32x2 packed math (sm_103a; ptxas never emits these from C++) ----
__device__ __forceinline__ ull ffma2(ull a, ull b, ull c) {
    ull d;
    asm("fma.rn.f32x2 %0, %1, %2, %3;" : "=l"(d) : "l"(a), "l"(b), "l"(c));
    return d;
}
__device__ __forceinline__ ull add2(ull a, ull b) {
    ull d;
    asm("add.rn.f32x2 %0, %1, %2;" : "=l"(d) : "l"(a), "l"(b));
    return d;
}
__device__ __forceinline__ ull bcast2(float x) {
    ull r;
    asm("mov.b64 %0, {%1, %1};" : "=l"(r) : "f"(x));
    return r;
}
__device__ __forceinline__ void unpack2(ull v, float& lo, float& hi) {
    asm("mov.b64 {%0, %1}, %2;" : "=f"(lo), "=f"(hi) : "l"(v));
}

// ---------------- persistent state (no allocations allowed) ----------------
// INVARIANT: g_deg all-zero at entry (BSS-zero first run; re-zeroed in last phase).
__device__ int g_bar_count;
__device__ int g_bar_sense;
__device__ int g_deg[NMAX];
__device__ int g_off[NMAX];
__device__ int g_cur[NMAX];
__device__ int g_csr[EMAX];
__device__ __align__(16) float g_p1[NMAX * 64];
__device__ __align__(16) float g_q1[NMAX * 64];
__device__ __align__(16) float g_h [NMAX * 64];
__device__ __align__(16) float g_p2[NMAX * 32];
__device__ __align__(16) float g_q2[NMAX * 32];

// ---------------- grid-wide barrier (sense reversal, volatile-load spin) ------------
__device__ __forceinline__ void gbar(int& sns) {
    __syncthreads();
    if (threadIdx.x == 0) {
        sns ^= 1;
        __threadfence();
        if (atomicAdd(&g_bar_count, 1) == NB - 1) {
            atomicExch(&g_bar_count, 0);
            __threadfence();
            *(volatile int*)&g_bar_sense = sns;
        } else {
            while (*(volatile int*)&g_bar_sense != sns) __nanosleep(32);
        }
        __threadfence();
    }
    __syncthreads();
}

// ---------------- the whole model in one launch ----------------
__global__ __launch_bounds__(NT, 4) void k_mono(
    const int* __restrict__ ei, const float* __restrict__ x,
    const float* __restrict__ W1l, const float* __restrict__ b1l,
    const float* __restrict__ W1r, const float* __restrict__ W2l,
    const float* __restrict__ b2l, const float* __restrict__ W2r,
    float* __restrict__ out, int n, int E)
{
    __shared__ __align__(16) float s_pool[10496];   // 41,984 B, reused across phases
    __shared__ int s_wsum[8];
    __shared__ int s_m;

    const int tid  = threadIdx.x;
    const int bid  = blockIdx.x;
    const int gtid = bid * NT + tid;
    const int lane = tid & 31;
    const int wid  = tid >> 5;

    // dtype detect: int64 LE values <1e5 -> all odd 32-bit words are 0
    if (tid == 0) {
        int orv = 0;
        #pragma unroll
        for (int k = 0; k < 64; k++) orv |= ei[2 * k + 1];
        s_m = (orv == 0) ? 2 : 1;
    }
    __syncthreads();
    const int m = s_m;

    int sns = 0;
    if (tid == 0) sns = *(volatile int*)&g_bar_sense;

    // ===== Phase A: degree count =====
    for (int e = gtid; e < E; e += GSZ) {
        int d = ei[((long long)E + e) * m];
        atomicAdd(&g_deg[d], 1);
    }
    gbar(sns);

    // ===== Phase B: block0 scans; blocks 1..NB-1 do layer-1 dual GEMM =====
    if (bid == 0) {
        int carry = 0;
        int nch = (n + 1023) >> 10;
        for (int c = 0; c < nch; c++) {
            int base = (c << 10) + tid * 4;
            int4 v4 = make_int4(0, 0, 0, 0);
            if (base + 3 < n) v4 = *reinterpret_cast<const int4*>(g_deg + base);
            else {
                if (base     < n) v4.x = g_deg[base];
                if (base + 1 < n) v4.y = g_deg[base + 1];
                if (base + 2 < n) v4.z = g_deg[base + 2];
            }
            int s0 = v4.x, s1 = s0 + v4.y, s2 = s1 + v4.z, s3 = s2 + v4.w;
            int v = s3;
            #pragma unroll
            for (int d = 1; d < 32; d <<= 1) {
                int t = __shfl_up_sync(0xffffffffu, v, d);
                if (lane >= d) v += t;
            }
            if (lane == 31) s_wsum[wid] = v;
            __syncthreads();
            if (tid < 8) {
                int w = s_wsum[tid];
                #pragma unroll
                for (int d = 1; d < 8; d <<= 1) {
                    int t = __shfl_up_sync(0xffu, w, d, 8);
                    if (tid >= d) w += t;
                }
                s_wsum[tid] = w;
            }
            __syncthreads();
            int pre = carry + (wid ? s_wsum[wid - 1] : 0) + (v - s3);
            if (base     < n) { g_off[base]     = pre;      g_cur[base]     = pre;      }
            if (base + 1 < n) { g_off[base + 1] = pre + s0; g_cur[base + 1] = pre + s0; }
            if (base + 2 < n) { g_off[base + 2] = pre + s1; g_cur[base + 2] = pre + s1; }
            if (base + 3 < n) { g_off[base + 3] = pre + s2; g_cur[base + 3] = pre + s2; }
            int tot = s_wsum[7];
            __syncthreads();
            carry += tot;
        }
    } else {
        // gemm64: p1 = x@W1l, q1 = x@W1r + b1; MT=32 nodes/tile, NC=128 cols; f32x2 core
        float* sW = s_pool;                                   // [64][128]
        float (*sXT)[36] = (float(*)[36])(s_pool + 8192);     // [64][36]
        for (int i = tid; i < 64 * 128; i += NT) {
            int k = i >> 7, c = i & 127;
            sW[i] = (c < 64) ? W1l[k * 64 + c] : W1r[k * 64 + (c - 64)];
        }
        int ntiles = (n + 31) >> 5;
        for (int t = bid - 1; t < ntiles; t += NB - 1) {
            int nodeBase = t << 5;
            __syncthreads();
            #pragma unroll
            for (int i = 0; i < 2; i++) {
                int flat = tid + i * NT;
                int nd = flat >> 4, k4 = (flat & 15) * 4;
                int node = nodeBase + nd;
                float4 v = make_float4(0.f, 0.f, 0.f, 0.f);
                if (node < n) v = *reinterpret_cast<const float4*>(x + (size_t)node * 64 + k4);
                sXT[k4 + 0][nd] = v.x; sXT[k4 + 1][nd] = v.y;
                sXT[k4 + 2][nd] = v.z; sXT[k4 + 3][nd] = v.w;
            }
            __syncthreads();
            int tn = tid & 31, tm = tid >> 5;
            ull acc[4][2];
            #pragma unroll
            for (int r = 0; r < 4; r++) { acc[r][0] = 0ull; acc[r][1] = 0ull; }
            #pragma unroll 8
            for (int k = 0; k < 64; k++) {
                ulonglong2 bv = *reinterpret_cast<const ulonglong2*>(&sW[k * 128 + tn * 4]);
                float4 av = *reinterpret_cast<const float4*>(&sXT[k][tm * 4]);
                ull aa0 = bcast2(av.x), aa1 = bcast2(av.y);
                ull aa2 = bcast2(av.z), aa3 = bcast2(av.w);
                acc[0][0] = ffma2(aa0, bv.x, acc[0][0]); acc[0][1] = ffma2(aa0, bv.y, acc[0][1]);
                acc[1][0] = ffma2(aa1, bv.x, acc[1][0]); acc[1][1] = ffma2(aa1, bv.y, acc[1][1]);
                acc[2][0] = ffma2(aa2, bv.x, acc[2][0]); acc[2][1] = ffma2(aa2, bv.y, acc[2][1]);
                acc[3][0] = ffma2(aa3, bv.x, acc[3][0]); acc[3][1] = ffma2(aa3, bv.y, acc[3][1]);
            }
            int cbase = tn * 4;
            bool isQ = (cbase >= 64);
            int col = isQ ? (cbase - 64) : cbase;
            float4 bias = make_float4(0.f, 0.f, 0.f, 0.f);
            if (isQ) bias = *reinterpret_cast<const float4*>(b1l + col);
            float* dst = isQ ? g_q1 : g_p1;
            #pragma unroll
            for (int r = 0; r < 4; r++) {
                int node = nodeBase + tm * 4 + r;
                if (node < n) {
                    float c0, c1, c2, c3;
                    unpack2(acc[r][0], c0, c1);
                    unpack2(acc[r][1], c2, c3);
                    float4 o = make_float4(c0 + bias.x, c1 + bias.y, c2 + bias.z, c3 + bias.w);
                    *reinterpret_cast<float4*>(dst + (size_t)node * 64 + col) = o;
                }
            }
        }
    }
    gbar(sns);

    // ===== Phase C: CSR scatter =====
    for (int e = gtid; e < E; e += GSZ) {
        int s = ei[(long long)e * m];
        int d = ei[((long long)E + e) * m];
        int pos = atomicAdd(&g_cur[d], 1);
        g_csr[pos] = s;
    }
    gbar(sns);

    // ===== Phase D: agg64 + relu — 2 edges/warp, 16 lanes x float4, f32x2 adds =====
    {
        const int half = lane >> 4, l16 = lane & 15;
        int gw = bid * 8 + wid;
        for (int node = gw; node < n; node += NWARPS) {
            int o = g_off[node];
            int d = g_deg[node];
            ull acc0 = 0ull, acc1 = 0ull;
            int e = 0;
            for (; e + 16 <= d; e += 16) {
                int idx[8];
                #pragma unroll
                for (int i = 0; i < 8; i++) idx[i] = __ldg(&g_csr[o + e + 2 * i + half]);
                #pragma unroll
                for (int i = 0; i < 8; i++) {
                    ulonglong2 v = __ldg((const ulonglong2*)(g_p1 + (size_t)idx[i] * 64 + l16 * 4));
                    acc0 = add2(acc0, v.x);
                    acc1 = add2(acc1, v.y);
                }
            }
            for (; e + 2 <= d; e += 2) {
                int s = __ldg(&g_csr[o + e + half]);
                ulonglong2 v = __ldg((const ulonglong2*)(g_p1 + (size_t)s * 64 + l16 * 4));
                acc0 = add2(acc0, v.x);
                acc1 = add2(acc1, v.y);
            }
            if (e < d && half == 0) {
                int s = __ldg(&g_csr[o + e]);
                ulonglong2 v = __ldg((const ulonglong2*)(g_p1 + (size_t)s * 64 + l16 * 4));
                acc0 = add2(acc0, v.x);
                acc1 = add2(acc1, v.y);
            }
            float a0, a1, a2, a3;
            unpack2(acc0, a0, a1);
            unpack2(acc1, a2, a3);
            a0 += __shfl_xor_sync(0xffffffffu, a0, 16);
            a1 += __shfl_xor_sync(0xffffffffu, a1, 16);
            a2 += __shfl_xor_sync(0xffffffffu, a2, 16);
            a3 += __shfl_xor_sync(0xffffffffu, a3, 16);
            if (half == 0) {
                float inv = 1.0f / (float)max(d, 1);
                float4 qq = __ldg((const float4*)(g_q1 + (size_t)node * 64 + l16 * 4));
                float4 ov;
                ov.x = fmaxf(fmaf(a0, inv, qq.x), 0.0f);
                ov.y = fmaxf(fmaf(a1, inv, qq.y), 0.0f);
                ov.z = fmaxf(fmaf(a2, inv, qq.z), 0.0f);
                ov.w = fmaxf(fmaf(a3, inv, qq.w), 0.0f);
                *reinterpret_cast<float4*>(g_h + (size_t)node * 64 + l16 * 4) = ov;
            }
        }
    }
    gbar(sns);

    // ===== Phase E: layer-2 dual GEMM: p2 = h@W2l, q2 = h@W2r + b2; f32x2 core =====
    {
        float* sW2 = s_pool;                                  // [64][64]
        float (*sXT2)[68] = (float(*)[68])(s_pool + 4096);    // [64][68]
        for (int i = tid; i < 64 * 64; i += NT) {
            int k = i >> 6, c = i & 63;
            sW2[i] = (c < 32) ? W2l[k * 32 + c] : W2r[k * 32 + (c - 32)];
        }
        int ntiles = (n + 63) >> 6;
        for (int t = bid; t < ntiles; t += NB) {
            int nodeBase = t << 6;
            __syncthreads();
            #pragma unroll
            for (int i = 0; i < 4; i++) {
                int flat = tid + i * NT;
                int nd = flat >> 4, k4 = (flat & 15) * 4;
                int node = nodeBase + nd;
                float4 v = make_float4(0.f, 0.f, 0.f, 0.f);
                if (node < n) v = *reinterpret_cast<const float4*>(g_h + (size_t)node * 64 + k4);
                sXT2[k4 + 0][nd] = v.x; sXT2[k4 + 1][nd] = v.y;
                sXT2[k4 + 2][nd] = v.z; sXT2[k4 + 3][nd] = v.w;
            }
            __syncthreads();
            int tn = tid & 15, tm = tid >> 4;
            ull acc[4][2];
            #pragma unroll
            for (int r = 0; r < 4; r++) { acc[r][0] = 0ull; acc[r][1] = 0ull; }
            #pragma unroll 8
            for (int k = 0; k < 64; k++) {
                ulonglong2 bv = *reinterpret_cast<const ulonglong2*>(&sW2[k * 64 + tn * 4]);
                float4 av = *reinterpret_cast<const float4*>(&sXT2[k][tm * 4]);
                ull aa0 = bcast2(av.x), aa1 = bcast2(av.y);
                ull aa2 = bcast2(av.z), aa3 = bcast2(av.w);
                acc[0][0] = ffma2(aa0, bv.x, acc[0][0]); acc[0][1] = ffma2(aa0, bv.y, acc[0][1]);
                acc[1][0] = ffma2(aa1, bv.x, acc[1][0]); acc[1][1] = ffma2(aa1, bv.y, acc[1][1]);
                acc[2][0] = ffma2(aa2, bv.x, acc[2][0]); acc[2][1] = ffma2(aa2, bv.y, acc[2][1]);
                acc[3][0] = ffma2(aa3, bv.x, acc[3][0]); acc[3][1] = ffma2(aa3, bv.y, acc[3][1]);
            }
            int cbase = tn * 4;
            bool isQ = (cbase >= 32);
            int col = isQ ? (cbase - 32) : cbase;
            float4 bias = make_float4(0.f, 0.f, 0.f, 0.f);
            if (isQ) bias = *reinterpret_cast<const float4*>(b2l + col);
            float* dst = isQ ? g_q2 : g_p2;
            #pragma unroll
            for (int r = 0; r < 4; r++) {
                int node = nodeBase + tm * 4 + r;
                if (node < n) {
                    float c0, c1, c2, c3;
                    unpack2(acc[r][0], c0, c1);
                    unpack2(acc[r][1], c2, c3);
                    float4 o = make_float4(c0 + bias.x, c1 + bias.y, c2 + bias.z, c3 + bias.w);
                    *reinterpret_cast<float4*>(dst + (size_t)node * 32 + col) = o;
                }
            }
        }
    }
    gbar(sns);

    // ===== Phase F: agg32 -> out — 4 edges/warp, 8 lanes x float4; restore deg=0 =====
    {
        const int q4 = lane >> 3, l8 = lane & 7;
        int gw = bid * 8 + wid;
        for (int node = gw; node < n; node += NWARPS) {
            int o = g_off[node];
            int d = g_deg[node];
            if (lane == 0) g_deg[node] = 0;
            ull acc0 = 0ull, acc1 = 0ull;
            int e = 0;
            for (; e + 16 <= d; e += 16) {
                int idx[4];
                #pragma unroll
                for (int i = 0; i < 4; i++) idx[i] = __ldg(&g_csr[o + e + 4 * i + q4]);
                #pragma unroll
                for (int i = 0; i < 4; i++) {
                    ulonglong2 v = __ldg((const ulonglong2*)(g_p2 + (size_t)idx[i] * 32 + l8 * 4));
                    acc0 = add2(acc0, v.x);
                    acc1 = add2(acc1, v.y);
                }
            }
            for (; e + 4 <= d; e += 4) {
                int s = __ldg(&g_csr[o + e + q4]);
                ulonglong2 v = __ldg((const ulonglong2*)(g_p2 + (size_t)s * 32 + l8 * 4));
                acc0 = add2(acc0, v.x);
                acc1 = add2(acc1, v.y);
            }
            int rem = d - e;
            if (q4 < rem) {
                int s = __ldg(&g_csr[o + e + q4]);
                ulonglong2 v = __ldg((const ulonglong2*)(g_p2 + (size_t)s * 32 + l8 * 4));
                acc0 = add2(acc0, v.x);
                acc1 = add2(acc1, v.y);
            }
            float a0, a1, a2, a3;
            unpack2(acc0, a0, a1);
            unpack2(acc1, a2, a3);
            a0 += __shfl_xor_sync(0xffffffffu, a0, 8);
            a1 += __shfl_xor_sync(0xffffffffu, a1, 8);
            a2 += __shfl_xor_sync(0xffffffffu, a2, 8);
            a3 += __shfl_xor_sync(0xffffffffu, a3, 8);
            a0 += __shfl_xor_sync(0xffffffffu, a0, 16);
            a1 += __shfl_xor_sync(0xffffffffu, a1, 16);
            a2 += __shfl_xor_sync(0xffffffffu, a2, 16);
            a3 += __shfl_xor_sync(0xffffffffu, a3, 16);
            if (q4 == 0) {
                float inv = 1.0f / (float)max(d, 1);
                float4 qq = __ldg((const float4*)(g_q2 + (size_t)node * 32 + l8 * 4));
                float4 o;
                o.x = fmaf(a0, inv, qq.x);
                o.y = fmaf(a1, inv, qq.y);
                o.z = fmaf(a2, inv, qq.z);
                o.w = fmaf(a3, inv, qq.w);
                *reinterpret_cast<float4*>(out + (size_t)node * 32 + l8 * 4) = o;
            }
        }
    }
}

// ---------------- launcher: ONE kernel ----------------
extern "C" void kernel_launch(void* const* d_in, const int* in_sizes, int n_in,
                              void* d_out, int out_size)
{
    const float* x   = (const float*)d_in[0];
    const int*   ei  = (const int*)d_in[1];
    const float* W1l = (const float*)d_in[2];
    const float* b1l = (const float*)d_in[3];
    const float* W1r = (const float*)d_in[4];
    const float* W2l = (const float*)d_in[5];
    const float* b2l = (const float*)d_in[6];
    const float* W2r = (const float*)d_in[7];
    float* out = (float*)d_out;

    int n = in_sizes[0] / 64;      // 100000
    int E = in_sizes[1] / 2;       // 1600000

    k_mono<<<NB, NT>>>(ei, x, W1l, b1l, W1r, W2l, b2l, W2r, out, n, E);
}

// round 10
// speedup vs baseline: 16.7502x; 1.2416x over previous
#include <cuda_runtime.h>

#define NMAX   100000
#define EMAX   1600000
#define NB     592            // 4 blocks/SM on 148 SMs -> co-resident
#define NT     256
#define GSZ    (NB * NT)
#define NWARPS (NB * 8)

typedef unsigned long long ull;

// ---------------- f32x2 packed math ----------------
__device__ __forceinline__ ull ffma2(ull a, ull b, ull c) {
    ull d;
    asm("fma.rn.f32x2 %0, %1, %2, %3;" : "=l"(d) : "l"(a), "l"(b), "l"(c));
    return d;
}
__device__ __forceinline__ ull add2(ull a, ull b) {
    ull d;
    asm("add.rn.f32x2 %0, %1, %2;" : "=l"(d) : "l"(a), "l"(b));
    return d;
}
__device__ __forceinline__ ull bcast2(float x) {
    ull r;
    asm("mov.b64 %0, {%1, %1};" : "=l"(r) : "f"(x));
    return r;
}
__device__ __forceinline__ void unpack2(ull v, float& lo, float& hi) {
    asm("mov.b64 {%0, %1}, %2;" : "=f"(lo), "=f"(hi) : "l"(v));
}

// ---------------- persistent state ----------------
// INVARIANT: g_deg all-zero at entry (BSS-zero first run; re-zeroed in last phase).
__device__ int g_bar_count;
__device__ int g_bar_sense;
__device__ int g_bsum[32];
__device__ int g_deg[NMAX];
__device__ int g_off[NMAX];
__device__ int g_cur[NMAX];
__device__ int g_csr[EMAX];
__device__ __align__(16) float g_p1[NMAX * 64];
__device__ __align__(16) float g_q1[NMAX * 64];
__device__ __align__(16) float g_p2[NMAX * 32];
__device__ __align__(16) float g_q2[NMAX * 32];

// ---------------- grid-wide barrier ----------------
__device__ __forceinline__ void gbar(int& sns) {
    __syncthreads();
    if (threadIdx.x == 0) {
        sns ^= 1;
        __threadfence();
        if (atomicAdd(&g_bar_count, 1) == NB - 1) {
            atomicExch(&g_bar_count, 0);
            __threadfence();
            *(volatile int*)&g_bar_sense = sns;
        } else {
            while (*(volatile int*)&g_bar_sense != sns) __nanosleep(32);
        }
        __threadfence();
    }
    __syncthreads();
}

__global__ __launch_bounds__(NT, 4) void k_mono(
    const int* __restrict__ ei, const float* __restrict__ x,
    const float* __restrict__ W1l, const float* __restrict__ b1l,
    const float* __restrict__ W1r, const float* __restrict__ W2l,
    const float* __restrict__ b2l, const float* __restrict__ W2r,
    float* __restrict__ out, int n, int E)
{
    __shared__ __align__(16) float s_pool[10496];   // reused across phases
    __shared__ int s_wsum[8];
    __shared__ int s_m;

    const int tid  = threadIdx.x;
    const int bid  = blockIdx.x;
    const int gtid = bid * NT + tid;
    const int lane = tid & 31;
    const int wid  = tid >> 5;

    if (tid == 0) {
        int orv = 0;
        #pragma unroll
        for (int k = 0; k < 64; k++) orv |= ei[2 * k + 1];
        s_m = (orv == 0) ? 2 : 1;
    }
    __syncthreads();
    const int m = s_m;

    int sns = 0;
    if (tid == 0) sns = *(volatile int*)&g_bar_sense;

    // ===== P1: degree count (all blocks) THEN layer-1 dual GEMM (all blocks) =====
    for (int e = gtid; e < E; e += GSZ) {
        int d = ei[((long long)E + e) * m];
        atomicAdd(&g_deg[d], 1);
    }
    {
        // gemm64: p1 = x@W1l, q1 = x@W1r + b1; MT=32 tiles, NC=128, f32x2 core
        float* sW = s_pool;                                   // [64][128]
        float (*sXT)[36] = (float(*)[36])(s_pool + 8192);     // [64][36]
        for (int i = tid; i < 64 * 128; i += NT) {
            int k = i >> 7, c = i & 127;
            sW[i] = (c < 64) ? W1l[k * 64 + c] : W1r[k * 64 + (c - 64)];
        }
        int ntiles = (n + 31) >> 5;
        for (int t = bid; t < ntiles; t += NB) {
            int nodeBase = t << 5;
            __syncthreads();
            #pragma unroll
            for (int i = 0; i < 2; i++) {
                int flat = tid + i * NT;
                int nd = flat >> 4, k4 = (flat & 15) * 4;
                int node = nodeBase + nd;
                float4 v = make_float4(0.f, 0.f, 0.f, 0.f);
                if (node < n) v = *reinterpret_cast<const float4*>(x + (size_t)node * 64 + k4);
                sXT[k4 + 0][nd] = v.x; sXT[k4 + 1][nd] = v.y;
                sXT[k4 + 2][nd] = v.z; sXT[k4 + 3][nd] = v.w;
            }
            __syncthreads();
            int tn = tid & 31, tm = tid >> 5;
            ull acc[4][2];
            #pragma unroll
            for (int r = 0; r < 4; r++) { acc[r][0] = 0ull; acc[r][1] = 0ull; }
            #pragma unroll 8
            for (int k = 0; k < 64; k++) {
                ulonglong2 bv = *reinterpret_cast<const ulonglong2*>(&sW[k * 128 + tn * 4]);
                float4 av = *reinterpret_cast<const float4*>(&sXT[k][tm * 4]);
                ull aa0 = bcast2(av.x), aa1 = bcast2(av.y);
                ull aa2 = bcast2(av.z), aa3 = bcast2(av.w);
                acc[0][0] = ffma2(aa0, bv.x, acc[0][0]); acc[0][1] = ffma2(aa0, bv.y, acc[0][1]);
                acc[1][0] = ffma2(aa1, bv.x, acc[1][0]); acc[1][1] = ffma2(aa1, bv.y, acc[1][1]);
                acc[2][0] = ffma2(aa2, bv.x, acc[2][0]); acc[2][1] = ffma2(aa2, bv.y, acc[2][1]);
                acc[3][0] = ffma2(aa3, bv.x, acc[3][0]); acc[3][1] = ffma2(aa3, bv.y, acc[3][1]);
            }
            int cbase = tn * 4;
            bool isQ = (cbase >= 64);
            int col = isQ ? (cbase - 64) : cbase;
            float4 bias = make_float4(0.f, 0.f, 0.f, 0.f);
            if (isQ) bias = *reinterpret_cast<const float4*>(b1l + col);
            float* dst = isQ ? g_q1 : g_p1;
            #pragma unroll
            for (int r = 0; r < 4; r++) {
                int node = nodeBase + tm * 4 + r;
                if (node < n) {
                    float c0, c1, c2, c3;
                    unpack2(acc[r][0], c0, c1);
                    unpack2(acc[r][1], c2, c3);
                    float4 o = make_float4(c0 + bias.x, c1 + bias.y, c2 + bias.z, c3 + bias.w);
                    *reinterpret_cast<float4*>(dst + (size_t)node * 64 + col) = o;
                }
            }
        }
    }
    gbar(sns);

    // ===== P2: parallel scan, step 1 — 25 blocks, 4096-elem chunks =====
    if (bid < 25) {
        int base = bid * 4096 + tid * 16;
        int v[16];
        #pragma unroll
        for (int g = 0; g < 4; g++) {
            int b4 = base + g * 4;
            int4 t4 = make_int4(0, 0, 0, 0);
            if (b4 + 3 < n) t4 = *reinterpret_cast<const int4*>(g_deg + b4);
            else {
                if (b4     < n) t4.x = g_deg[b4];
                if (b4 + 1 < n) t4.y = g_deg[b4 + 1];
                if (b4 + 2 < n) t4.z = g_deg[b4 + 2];
            }
            v[g * 4 + 0] = t4.x; v[g * 4 + 1] = t4.y;
            v[g * 4 + 2] = t4.z; v[g * 4 + 3] = t4.w;
        }
        int s[16];
        s[0] = v[0];
        #pragma unroll
        for (int j = 1; j < 16; j++) s[j] = s[j - 1] + v[j];
        int tot = s[15];
        int incl = tot;
        #pragma unroll
        for (int d = 1; d < 32; d <<= 1) {
            int t = __shfl_up_sync(0xffffffffu, incl, d);
            if (lane >= d) incl += t;
        }
        if (lane == 31) s_wsum[wid] = incl;
        __syncthreads();
        if (tid < 8) {
            int w = s_wsum[tid];
            #pragma unroll
            for (int d = 1; d < 8; d <<= 1) {
                int t = __shfl_up_sync(0xffu, w, d, 8);
                if (tid >= d) w += t;
            }
            s_wsum[tid] = w;
        }
        __syncthreads();
        int pre = (wid ? s_wsum[wid - 1] : 0) + (incl - tot);
        #pragma unroll
        for (int g = 0; g < 4; g++) {
            int b4 = base + g * 4;
            int4 o;
            o.x = pre + (g * 4     ? s[g * 4 - 1] : 0);
            o.y = pre + s[g * 4 + 0];
            o.z = pre + s[g * 4 + 1];
            o.w = pre + s[g * 4 + 2];
            if (b4 + 3 < n) *reinterpret_cast<int4*>(g_off + b4) = o;
            else {
                if (b4     < n) g_off[b4]     = o.x;
                if (b4 + 1 < n) g_off[b4 + 1] = o.y;
                if (b4 + 2 < n) g_off[b4 + 2] = o.z;
            }
        }
        if (tid == 0) g_bsum[bid] = 0;        // placeholder; set below
        __syncthreads();
        if (tid == NT - 1) g_bsum[bid] = s_wsum[7];
    }
    gbar(sns);

    // ===== P3: scan the 25 block sums (block0, 1 warp) =====
    if (bid == 0 && tid < 32) {
        int v = (tid < 25) ? g_bsum[tid] : 0;
        int incl = v;
        #pragma unroll
        for (int d = 1; d < 32; d <<= 1) {
            int t = __shfl_up_sync(0xffffffffu, incl, d);
            if (tid >= d) incl += t;
        }
        if (tid < 25) g_bsum[tid] = incl - v;   // exclusive
    }
    gbar(sns);

    // ===== P4: add bases, write cur =====
    if (bid < 25) {
        int add = g_bsum[bid];
        #pragma unroll
        for (int g = 0; g < 4; g++) {
            int b4 = bid * 4096 + tid * 4 + g * 1024;
            if (b4 + 3 < n) {
                int4 o = *reinterpret_cast<const int4*>(g_off + b4);
                o.x += add; o.y += add; o.z += add; o.w += add;
                *reinterpret_cast<int4*>(g_off + b4) = o;
                *reinterpret_cast<int4*>(g_cur + b4) = o;
            } else {
                for (int j = 0; j < 4; j++) {
                    if (b4 + j < n) {
                        int o = g_off[b4 + j] + add;
                        g_off[b4 + j] = o;
                        g_cur[b4 + j] = o;
                    }
                }
            }
        }
    }
    gbar(sns);

    // ===== P5: CSR scatter =====
    for (int e = gtid; e < E; e += GSZ) {
        int s = ei[(long long)e * m];
        int d = ei[((long long)E + e) * m];
        int pos = atomicAdd(&g_cur[d], 1);
        g_csr[pos] = s;
    }
    gbar(sns);

    // ===== P6: FUSED agg64+relu (h kept in smem, transposed) + layer-2 dual GEMM =====
    {
        float* sW2 = s_pool;                                  // [64][64] = [Wl|Wr] k-major
        float (*sXT2)[68] = (float(*)[68])(s_pool + 4096);    // h^T tile [64k][64node+pad]
        for (int i = tid; i < 64 * 64; i += NT) {
            int k = i >> 6, c = i & 63;
            sW2[i] = (c < 32) ? W2l[k * 32 + c] : W2r[k * 32 + (c - 32)];
        }
        const int half = lane >> 4, l16 = lane & 15;
        int ntiles = (n + 63) >> 6;
        for (int t = bid; t < ntiles; t += NB) {
            int tbase = t << 6;
            __syncthreads();   // protect smem from previous tile's MMA readers
            // --- aggregate 8 nodes per warp; write relu(h) transposed into smem ---
            #pragma unroll 1
            for (int i = 0; i < 8; i++) {
                int ndl = wid * 8 + i;
                int node = tbase + ndl;
                if (node >= n) break;
                int o = g_off[node];
                int d = g_deg[node];
                ull acc0 = 0ull, acc1 = 0ull;
                int e = 0;
                for (; e + 16 <= d; e += 16) {
                    int idx[8];
                    #pragma unroll
                    for (int j = 0; j < 8; j++) idx[j] = __ldg(&g_csr[o + e + 2 * j + half]);
                    #pragma unroll
                    for (int j = 0; j < 8; j++) {
                        ulonglong2 v = __ldg((const ulonglong2*)(g_p1 + (size_t)idx[j] * 64 + l16 * 4));
                        acc0 = add2(acc0, v.x);
                        acc1 = add2(acc1, v.y);
                    }
                }
                for (; e + 2 <= d; e += 2) {
                    int s = __ldg(&g_csr[o + e + half]);
                    ulonglong2 v = __ldg((const ulonglong2*)(g_p1 + (size_t)s * 64 + l16 * 4));
                    acc0 = add2(acc0, v.x);
                    acc1 = add2(acc1, v.y);
                }
                if (e < d && half == 0) {
                    int s = __ldg(&g_csr[o + e]);
                    ulonglong2 v = __ldg((const ulonglong2*)(g_p1 + (size_t)s * 64 + l16 * 4));
                    acc0 = add2(acc0, v.x);
                    acc1 = add2(acc1, v.y);
                }
                float a0, a1, a2, a3;
                unpack2(acc0, a0, a1);
                unpack2(acc1, a2, a3);
                a0 += __shfl_xor_sync(0xffffffffu, a0, 16);
                a1 += __shfl_xor_sync(0xffffffffu, a1, 16);
                a2 += __shfl_xor_sync(0xffffffffu, a2, 16);
                a3 += __shfl_xor_sync(0xffffffffu, a3, 16);
                if (half == 0) {
                    float inv = 1.0f / (float)max(d, 1);
                    float4 qq = __ldg((const float4*)(g_q1 + (size_t)node * 64 + l16 * 4));
                    sXT2[l16 * 4 + 0][ndl] = fmaxf(fmaf(a0, inv, qq.x), 0.0f);
                    sXT2[l16 * 4 + 1][ndl] = fmaxf(fmaf(a1, inv, qq.y), 0.0f);
                    sXT2[l16 * 4 + 2][ndl] = fmaxf(fmaf(a2, inv, qq.z), 0.0f);
                    sXT2[l16 * 4 + 3][ndl] = fmaxf(fmaf(a3, inv, qq.w), 0.0f);
                }
            }
            __syncthreads();
            // --- gemm32 on the smem-resident h tile ---
            int tn = tid & 15, tm = tid >> 4;
            ull acc[4][2];
            #pragma unroll
            for (int r = 0; r < 4; r++) { acc[r][0] = 0ull; acc[r][1] = 0ull; }
            #pragma unroll 8
            for (int k = 0; k < 64; k++) {
                ulonglong2 bv = *reinterpret_cast<const ulonglong2*>(&sW2[k * 64 + tn * 4]);
                float4 av = *reinterpret_cast<const float4*>(&sXT2[k][tm * 4]);
                ull aa0 = bcast2(av.x), aa1 = bcast2(av.y);
                ull aa2 = bcast2(av.z), aa3 = bcast2(av.w);
                acc[0][0] = ffma2(aa0, bv.x, acc[0][0]); acc[0][1] = ffma2(aa0, bv.y, acc[0][1]);
                acc[1][0] = ffma2(aa1, bv.x, acc[1][0]); acc[1][1] = ffma2(aa1, bv.y, acc[1][1]);
                acc[2][0] = ffma2(aa2, bv.x, acc[2][0]); acc[2][1] = ffma2(aa2, bv.y, acc[2][1]);
                acc[3][0] = ffma2(aa3, bv.x, acc[3][0]); acc[3][1] = ffma2(aa3, bv.y, acc[3][1]);
            }
            int cbase = tn * 4;
            bool isQ = (cbase >= 32);
            int col = isQ ? (cbase - 32) : cbase;
            float4 bias = make_float4(0.f, 0.f, 0.f, 0.f);
            if (isQ) bias = *reinterpret_cast<const float4*>(b2l + col);
            float* dst = isQ ? g_q2 : g_p2;
            #pragma unroll
            for (int r = 0; r < 4; r++) {
                int node = tbase + tm * 4 + r;
                if (node < n) {
                    float c0, c1, c2, c3;
                    unpack2(acc[r][0], c0, c1);
                    unpack2(acc[r][1], c2, c3);
                    float4 o = make_float4(c0 + bias.x, c1 + bias.y, c2 + bias.z, c3 + bias.w);
                    *reinterpret_cast<float4*>(dst + (size_t)node * 32 + col) = o;
                }
            }
        }
    }
    gbar(sns);

    // ===== P7: agg32 -> out; restore deg==0 invariant =====
    {
        const int q4 = lane >> 3, l8 = lane & 7;
        int gw = bid * 8 + wid;
        for (int node = gw; node < n; node += NWARPS) {
            int o = g_off[node];
            int d = g_deg[node];
            if (lane == 0) g_deg[node] = 0;
            ull acc0 = 0ull, acc1 = 0ull;
            int e = 0;
            for (; e + 16 <= d; e += 16) {
                int idx[4];
                #pragma unroll
                for (int i = 0; i < 4; i++) idx[i] = __ldg(&g_csr[o + e + 4 * i + q4]);
                #pragma unroll
                for (int i = 0; i < 4; i++) {
                    ulonglong2 v = __ldg((const ulonglong2*)(g_p2 + (size_t)idx[i] * 32 + l8 * 4));
                    acc0 = add2(acc0, v.x);
                    acc1 = add2(acc1, v.y);
                }
            }
            for (; e + 4 <= d; e += 4) {
                int s = __ldg(&g_csr[o + e + q4]);
                ulonglong2 v = __ldg((const ulonglong2*)(g_p2 + (size_t)s * 32 + l8 * 4));
                acc0 = add2(acc0, v.x);
                acc1 = add2(acc1, v.y);
            }
            int rem = d - e;
            if (q4 < rem) {
                int s = __ldg(&g_csr[o + e + q4]);
                ulonglong2 v = __ldg((const ulonglong2*)(g_p2 + (size_t)s * 32 + l8 * 4));
                acc0 = add2(acc0, v.x);
                acc1 = add2(acc1, v.y);
            }
            float a0, a1, a2, a3;
            unpack2(acc0, a0, a1);
            unpack2(acc1, a2, a3);
            a0 += __shfl_xor_sync(0xffffffffu, a0, 8);
            a1 += __shfl_xor_sync(0xffffffffu, a1, 8);
            a2 += __shfl_xor_sync(0xffffffffu, a2, 8);
            a3 += __shfl_xor_sync(0xffffffffu, a3, 8);
            a0 += __shfl_xor_sync(0xffffffffu, a0, 16);
            a1 += __shfl_xor_sync(0xffffffffu, a1, 16);
            a2 += __shfl_xor_sync(0xffffffffu, a2, 16);
            a3 += __shfl_xor_sync(0xffffffffu, a3, 16);
            if (q4 == 0) {
                float inv = 1.0f / (float)max(d, 1);
                float4 qq = __ldg((const float4*)(g_q2 + (size_t)node * 32 + l8 * 4));
                float4 o;
                o.x = fmaf(a0, inv, qq.x);
                o.y = fmaf(a1, inv, qq.y);
                o.z = fmaf(a2, inv, qq.z);
                o.w = fmaf(a3, inv, qq.w);
                *reinterpret_cast<float4*>(out + (size_t)node * 32 + l8 * 4) = o;
            }
        }
    }
}

// ---------------- launcher: ONE kernel ----------------
extern "C" void kernel_launch(void* const* d_in, const int* in_sizes, int n_in,
                              void* d_out, int out_size)
{
    const float* x   = (const float*)d_in[0];
    const int*   ei  = (const int*)d_in[1];
    const float* W1l = (const float*)d_in[2];
    const float* b1l = (const float*)d_in[3];
    const float* W1r = (const float*)d_in[4];
    const float* W2l = (const float*)d_in[5];
    const float* b2l = (const float*)d_in[6];
    const float* W2r = (const float*)d_in[7];
    float* out = (float*)d_out;

    int n = in_sizes[0] / 64;      // 100000
    int E = in_sizes[1] / 2;       // 1600000

    k_mono<<<NB, NT>>>(ei, x, W1l, b1l, W1r, W2l, b2l, W2r, out, n, E);
}